// round 13
// baseline (speedup 1.0000x reference)
#include <cuda_runtime.h>
#include <cuda_bf16.h>
#include <math.h>
#include <cstdint>

// ---------------------------------------------------------------------------
// Problem constants
// ---------------------------------------------------------------------------
#define BB   2
#define NN   2048
#define DD   2048
#define HH   16
#define HKV  4
#define HD   128
#define GG   (HH / HKV)
#define QKVW (HH * HD + 2 * HKV * HD)     // 3072: Q(2048) | K(512) | V(512)
#define KOFF (HH * HD)                    // 2048
#define VOFF (HH * HD + HKV * HD)         // 2560
#define SCALE 0.08838834764831845f

#define BK 64                  // K-chunk (fp32 elements) for gemm
#define TSTR 144               // gemm smem row stride bytes (128 data + 16 pad)
#define TILE_B (128 * TSTR)    // 18432
#define STAGE_B (4 * TILE_B)   // 73728
#define SMEM_SZ (2 * STAGE_B)  // 147456 (gemm, double buffered)
#define OFF_AHI 0
#define OFF_ALO (TILE_B)
#define OFF_BHI (2 * TILE_B)
#define OFF_BLO (3 * TILE_B)

// flash-attention smem layout (bytes) — full hi/lo P (R11 numerics)
#define KSTR 272               // 128 bf16 cols (256B) + 16 pad
#define VSTR 144               // 64 bf16 cols (128B) + 16 pad
#define F_QHI 0
#define F_QLO (F_QHI + 128 * KSTR)
#define F_KHI (F_QLO + 128 * KSTR)
#define F_KLO (F_KHI + 64 * KSTR)
#define F_VHI (F_KLO + 64 * KSTR)
#define F_VLO (F_VHI + 128 * VSTR)
#define F_PHI (F_VLO + 128 * VSTR)
#define F_PLO (F_PHI + 128 * VSTR)
#define F_SZ  (F_PLO + 128 * VSTR)    // 178176

// ---------------------------------------------------------------------------
// Device scratch
// ---------------------------------------------------------------------------
__device__ float g_QKV[(size_t)BB * NN * QKVW];            // 48 MB
__device__ float g_WT [(size_t)QKVW * DD];                 // 24 MB
__device__ float g_WoT[(size_t)DD * DD];                   // 16 MB
__device__ float g_ctx[(size_t)BB * NN * HH * HD];         // 32 MB

// pre-split bf16 hi/lo attention operands (flash only)
__device__ __align__(128) __nv_bfloat16 g_Qh [(size_t)BB * NN * HH * HD];
__device__ __align__(128) __nv_bfloat16 g_Ql [(size_t)BB * NN * HH * HD];
__device__ __align__(128) __nv_bfloat16 g_Kh [(size_t)BB * NN * HKV * HD];
__device__ __align__(128) __nv_bfloat16 g_Kl [(size_t)BB * NN * HKV * HD];
__device__ __align__(128) __nv_bfloat16 g_Vth[(size_t)BB * HKV * HD * NN];
__device__ __align__(128) __nv_bfloat16 g_Vtl[(size_t)BB * HKV * HD * NN];

// ---------------------------------------------------------------------------
// PTX helpers
// ---------------------------------------------------------------------------
__device__ __forceinline__ uint32_t smem_u32(const void* p) {
    uint32_t a;
    asm("{ .reg .u64 t; cvta.to.shared.u64 t, %1; cvt.u32.u64 %0, t; }" : "=r"(a) : "l"(p));
    return a;
}
__device__ __forceinline__ void ldmx4(uint32_t& r0, uint32_t& r1, uint32_t& r2, uint32_t& r3, uint32_t addr) {
    asm volatile("ldmatrix.sync.aligned.m8n8.x4.shared.b16 {%0,%1,%2,%3}, [%4];"
                 : "=r"(r0), "=r"(r1), "=r"(r2), "=r"(r3) : "r"(addr));
}
__device__ __forceinline__ void mma16816(float* c, const uint32_t* a, const uint32_t* b) {
    asm volatile(
        "mma.sync.aligned.m16n8k16.row.col.f32.bf16.bf16.f32 "
        "{%0,%1,%2,%3}, {%4,%5,%6,%7}, {%8,%9}, {%0,%1,%2,%3};"
        : "+f"(c[0]), "+f"(c[1]), "+f"(c[2]), "+f"(c[3])
        : "r"(a[0]), "r"(a[1]), "r"(a[2]), "r"(a[3]), "r"(b[0]), "r"(b[1]));
}

__device__ __forceinline__ void split4(float4 v, uint2& hi, uint2& lo) {
    __nv_bfloat16 hx = __float2bfloat16(v.x), hy = __float2bfloat16(v.y),
                  hz = __float2bfloat16(v.z), hw = __float2bfloat16(v.w);
    __nv_bfloat162 h01 = __halves2bfloat162(hx, hy), h23 = __halves2bfloat162(hz, hw);
    __nv_bfloat16 lx = __float2bfloat16(v.x - __bfloat162float(hx));
    __nv_bfloat16 ly = __float2bfloat16(v.y - __bfloat162float(hy));
    __nv_bfloat16 lz = __float2bfloat16(v.z - __bfloat162float(hz));
    __nv_bfloat16 lw = __float2bfloat16(v.w - __bfloat162float(hw));
    __nv_bfloat162 l01 = __halves2bfloat162(lx, ly), l23 = __halves2bfloat162(lz, lw);
    hi = make_uint2(*(uint32_t*)&h01, *(uint32_t*)&h23);
    lo = make_uint2(*(uint32_t*)&l01, *(uint32_t*)&l23);
}
__device__ __forceinline__ void split2(float a, float b, uint32_t& hi, uint32_t& lo) {
    __nv_bfloat16 ha = __float2bfloat16(a), hb = __float2bfloat16(b);
    __nv_bfloat16 la = __float2bfloat16(a - __bfloat162float(ha));
    __nv_bfloat16 lb = __float2bfloat16(b - __bfloat162float(hb));
    __nv_bfloat162 hp = __halves2bfloat162(ha, hb), lp = __halves2bfloat162(la, lb);
    hi = *(uint32_t*)&hp; lo = *(uint32_t*)&lp;
}
__device__ __forceinline__ void split1(float v, __nv_bfloat16& h, __nv_bfloat16& l) {
    h = __float2bfloat16(v);
    l = __float2bfloat16(v - __bfloat162float(h));
}

// gemm stage store — BK=64, 512 threads: 4 float4 per tile per thread
__device__ __forceinline__ void store_stage(char* sb, int t, const float4* pa, const float4* pb) {
    #pragma unroll
    for (int i = 0; i < 4; ++i) {
        int idx = t + i * 512, row = idx >> 4, c4 = idx & 15;
        uint32_t off = (uint32_t)(row * TSTR + c4 * 8);
        uint2 hi, lo;
        split4(pa[i], hi, lo);
        *(uint2*)(sb + OFF_AHI + off) = hi;
        *(uint2*)(sb + OFF_ALO + off) = lo;
        split4(pb[i], hi, lo);
        *(uint2*)(sb + OFF_BHI + off) = hi;
        *(uint2*)(sb + OFF_BLO + off) = lo;
    }
}

// ---------------------------------------------------------------------------
// GEMM mainloop — unchanged from R11 (512 thr, 16 warps, BK=64, double buffer)
// ---------------------------------------------------------------------------
__device__ __forceinline__ void mma_mainloop(
    const float* __restrict__ A, int lda,
    const float* __restrict__ B, int ldb, int K,
    float c[2][4][4])
{
    extern __shared__ __align__(16) char smem[];
    const int t    = threadIdx.x;
    const int lane = t & 31;
    const int warp = t >> 5;
    const int wm   = warp >> 2;
    const int wn   = warp & 3;
    const uint32_t sm = smem_u32(smem);

    const uint32_t a_off = (uint32_t)((wm * 32 + (lane & 15)) * TSTR + (lane >> 4) * 16);
    const uint32_t b_off = (uint32_t)(OFF_BHI + (wn * 32 + ((lane >> 4) * 8) + (lane & 7)) * TSTR + ((lane >> 3) & 1) * 16);

    float4 pa[4], pb[4];
    const int nch = K / BK;

    #pragma unroll
    for (int i = 0; i < 4; ++i) {
        int idx = t + i * 512, row = idx >> 4, c4 = idx & 15;
        pa[i] = *(const float4*)(A + (size_t)row * lda + c4 * 4);
        pb[i] = *(const float4*)(B + (size_t)row * ldb + c4 * 4);
    }
    store_stage(smem, t, pa, pb);
    __syncthreads();

    uint32_t buf = 0;
    for (int ch = 0; ch < nch; ++ch) {
        if (ch + 1 < nch) {
            const int k0 = (ch + 1) * BK;
            #pragma unroll
            for (int i = 0; i < 4; ++i) {
                int idx = t + i * 512, row = idx >> 4, c4 = idx & 15;
                pa[i] = *(const float4*)(A + (size_t)row * lda + k0 + c4 * 4);
                pb[i] = *(const float4*)(B + (size_t)row * ldb + k0 + c4 * 4);
            }
        }
        const uint32_t sb = sm + buf * STAGE_B;
        #pragma unroll
        for (int ks = 0; ks < 4; ++ks) {
            uint32_t ah[2][4], al[2][4], bh[4][2], bl[4][2];
            #pragma unroll
            for (int mt = 0; mt < 2; ++mt) {
                uint32_t ad = sb + a_off + (uint32_t)(mt * 16 * TSTR + ks * 32);
                ldmx4(ah[mt][0], ah[mt][1], ah[mt][2], ah[mt][3], ad + OFF_AHI);
                ldmx4(al[mt][0], al[mt][1], al[mt][2], al[mt][3], ad + OFF_ALO);
            }
            #pragma unroll
            for (int np = 0; np < 2; ++np) {
                uint32_t ad = sb + b_off + (uint32_t)(np * 16 * TSTR + ks * 32);
                ldmx4(bh[np * 2][0], bh[np * 2][1], bh[np * 2 + 1][0], bh[np * 2 + 1][1], ad);
                ldmx4(bl[np * 2][0], bl[np * 2][1], bl[np * 2 + 1][0], bl[np * 2 + 1][1], ad + TILE_B);
            }
            #pragma unroll
            for (int mt = 0; mt < 2; ++mt)
                #pragma unroll
                for (int nt = 0; nt < 4; ++nt) {
                    mma16816(c[mt][nt], ah[mt], bh[nt]);
                    mma16816(c[mt][nt], ah[mt], bl[nt]);
                    mma16816(c[mt][nt], al[mt], bh[nt]);
                }
        }
        if (ch + 1 < nch)
            store_stage(smem + (buf ^ 1) * STAGE_B, t, pa, pb);
        __syncthreads();
        buf ^= 1;
    }
}

#define ACC_INIT4(c) \
    _Pragma("unroll") for (int mt = 0; mt < 2; ++mt) \
    _Pragma("unroll") for (int nt = 0; nt < 4; ++nt) \
    _Pragma("unroll") for (int i = 0; i < 4; ++i) c[mt][nt][i] = 0.f

// ---------------------------------------------------------------------------
// Generic NT GEMM (unchanged from R11)
// ---------------------------------------------------------------------------
__global__ __launch_bounds__(512) void gemm_nt_mma(
    const float* __restrict__ A, int lda,
    const float* __restrict__ B, int ldb,
    float* __restrict__ C, int ldc, int K,
    const float* __restrict__ bias)
{
    const int m0 = blockIdx.y * 128, n0 = blockIdx.x * 128;
    float c[2][4][4];
    ACC_INIT4(c);

    mma_mainloop(A + (size_t)m0 * lda, lda, B + (size_t)n0 * ldb, ldb, K, c);

    const int lane = threadIdx.x & 31, warp = threadIdx.x >> 5;
    const int rb = m0 + (warp >> 2) * 32 + (lane >> 2);
    const int cb = n0 + (warp & 3) * 32 + (lane & 3) * 2;
    #pragma unroll
    for (int mt = 0; mt < 2; ++mt)
        #pragma unroll
        for (int nt = 0; nt < 4; ++nt) {
            int row = rb + mt * 16, col = cb + nt * 8;
            float b0 = bias ? bias[col] : 0.f, b1 = bias ? bias[col + 1] : 0.f;
            *(float2*)(C + (size_t)row * ldc + col)       = make_float2(c[mt][nt][0] + b0, c[mt][nt][1] + b1);
            *(float2*)(C + (size_t)(row + 8) * ldc + col) = make_float2(c[mt][nt][2] + b0, c[mt][nt][3] + b1);
        }
}

// ---------------------------------------------------------------------------
// Fused flash attention — R11 numerics (full 3-MMA hi/lo for QK and PV),
// with REGISTER PREFETCH of next K/V chunk overlapped under the MMA phases.
// ---------------------------------------------------------------------------
__global__ __launch_bounds__(256) void flash_attn(const float* __restrict__ mask)
{
    extern __shared__ __align__(16) char smem[];
    const int z = blockIdx.z, b = z / HH, h = z % HH, hkv = h % HKV;
    const int m0 = blockIdx.y * 128;
    const int t = threadIdx.x, lane = t & 31, w = t >> 5;
    const uint32_t sm = smem_u32(smem);

    // ---- load Q tile [128 x HD] bf16 hi/lo (once) ----
    {
        const __nv_bfloat16* Qh = g_Qh + ((size_t)(b * NN + m0) * HH + h) * HD;
        const __nv_bfloat16* Ql = g_Ql + ((size_t)(b * NN + m0) * HH + h) * HD;
        #pragma unroll
        for (int i = 0; i < 8; ++i) {
            int idx = t + i * 256, row = idx >> 4, c16 = idx & 15;
            uint32_t off = (uint32_t)(row * KSTR + c16 * 16);
            size_t g = (size_t)row * (HH * HD) + c16 * 8;
            *(uint4*)(smem + F_QHI + off) = *(const uint4*)(Qh + g);
            *(uint4*)(smem + F_QLO + off) = *(const uint4*)(Ql + g);
        }
    }

    // K/V base pointers + per-thread loader indices
    const __nv_bfloat16* Khb = g_Kh + (size_t)b * NN * HKV * HD + (size_t)hkv * HD;
    const __nv_bfloat16* Klb = g_Kl + (size_t)b * NN * HKV * HD + (size_t)hkv * HD;
    const __nv_bfloat16* Vhb = g_Vth + (size_t)(b * HKV + hkv) * HD * NN;
    const __nv_bfloat16* Vlb = g_Vtl + (size_t)(b * HKV + hkv) * HD * NN;
    const int krow = t >> 4, kc16 = t & 15;   // K: rows 0..15 step 16 -> 4 iters cover 64 rows
    const int vrow = t >> 3, vc16 = t & 7;    // V: rows 0..31 step 32 -> 4 iters cover 128 rows

    uint4 pkh[4], pkl[4], pvh[4], pvl[4];

    // prefetch chunk 0
    #pragma unroll
    for (int i = 0; i < 4; ++i) {
        int kr = krow + i * 16;
        size_t gk = ((size_t)kr) * (HKV * HD) + kc16 * 8;   // row within chunk; chunk offset added via n0
        pkh[i] = *(const uint4*)(Khb + gk);
        pkl[i] = *(const uint4*)(Klb + gk);
        int vr = vrow + i * 32;
        size_t gv = (size_t)vr * NN + vc16 * 8;
        pvh[i] = *(const uint4*)(Vhb + gv);
        pvl[i] = *(const uint4*)(Vlb + gv);
    }
    // store chunk 0 to smem
    #pragma unroll
    for (int i = 0; i < 4; ++i) {
        int kr = krow + i * 16;
        uint32_t koff = (uint32_t)(kr * KSTR + kc16 * 16);
        *(uint4*)(smem + F_KHI + koff) = pkh[i];
        *(uint4*)(smem + F_KLO + koff) = pkl[i];
        int vr = vrow + i * 32;
        uint32_t voff = (uint32_t)(vr * VSTR + vc16 * 16);
        *(uint4*)(smem + F_VHI + voff) = pvh[i];
        *(uint4*)(smem + F_VLO + voff) = pvl[i];
    }

    float co[16][4];
    #pragma unroll
    for (int nt = 0; nt < 16; ++nt)
        #pragma unroll
        for (int i = 0; i < 4; ++i) co[nt][i] = 0.f;
    float m0r = -INFINITY, m1r = -INFINITY;
    float l0r = 0.f, l1r = 0.f;

    const uint32_t qa_off = (uint32_t)((w * 16 + (lane & 15)) * KSTR + (lane >> 4) * 16);
    const uint32_t kb_base = (uint32_t)(((lane >> 4) * 8 + (lane & 7)) * KSTR + ((lane >> 3) & 1) * 16);
    const uint32_t pa_off = (uint32_t)((w * 16 + (lane & 15)) * VSTR + (lane >> 4) * 16);
    const uint32_t vb_base = (uint32_t)(((lane >> 4) * 8 + (lane & 7)) * VSTR + ((lane >> 3) & 1) * 16);

    __syncthreads();

    const int nch = NN / 64;
    for (int ch = 0; ch < nch; ++ch) {
        const int n0 = ch * 64;

        // ---- issue next chunk's K/V LDGs (latency hides under MMAs) ----
        if (ch + 1 < nch) {
            const int n1 = (ch + 1) * 64;
            #pragma unroll
            for (int i = 0; i < 4; ++i) {
                int kr = krow + i * 16;
                size_t gk = ((size_t)(n1 + kr)) * (HKV * HD) + kc16 * 8;
                pkh[i] = *(const uint4*)(Khb + gk);
                pkl[i] = *(const uint4*)(Klb + gk);
                int vr = vrow + i * 32;
                size_t gv = (size_t)vr * NN + n1 + vc16 * 8;
                pvh[i] = *(const uint4*)(Vhb + gv);
                pvl[i] = *(const uint4*)(Vlb + gv);
            }
        }

        // ---- S = Q @ Kc^T : warp computes 16 x 64 ----
        float cs[8][4];
        #pragma unroll
        for (int nt = 0; nt < 8; ++nt)
            #pragma unroll
            for (int i = 0; i < 4; ++i) cs[nt][i] = 0.f;

        #pragma unroll
        for (int ks = 0; ks < 8; ++ks) {
            uint32_t ah[4], al[4];
            uint32_t ad = sm + qa_off + (uint32_t)(ks * 32);
            ldmx4(ah[0], ah[1], ah[2], ah[3], ad + F_QHI);
            ldmx4(al[0], al[1], al[2], al[3], ad + F_QLO);
            #pragma unroll
            for (int np = 0; np < 4; ++np) {
                uint32_t bd = sm + kb_base + (uint32_t)(np * 16 * KSTR + ks * 32);
                uint32_t bh[2][2], bl[2][2];
                ldmx4(bh[0][0], bh[0][1], bh[1][0], bh[1][1], bd + F_KHI);
                ldmx4(bl[0][0], bl[0][1], bl[1][0], bl[1][1], bd + F_KLO);
                #pragma unroll
                for (int q = 0; q < 2; ++q) {
                    mma16816(cs[np * 2 + q], ah, bh[q]);
                    mma16816(cs[np * 2 + q], ah, bl[q]);
                    mma16816(cs[np * 2 + q], al, bh[q]);
                }
            }
        }

        // ---- scale + mask bias ----
        #pragma unroll
        for (int nt = 0; nt < 8; ++nt) {
            int col = n0 + nt * 8 + (lane & 3) * 2;
            float mb0 = (1.0f - mask[b * NN + col]) * -1e9f;
            float mb1 = (1.0f - mask[b * NN + col + 1]) * -1e9f;
            cs[nt][0] = cs[nt][0] * SCALE + mb0;
            cs[nt][1] = cs[nt][1] * SCALE + mb1;
            cs[nt][2] = cs[nt][2] * SCALE + mb0;
            cs[nt][3] = cs[nt][3] * SCALE + mb1;
        }

        // ---- online softmax ----
        float cm0 = -INFINITY, cm1 = -INFINITY;
        #pragma unroll
        for (int nt = 0; nt < 8; ++nt) {
            cm0 = fmaxf(cm0, fmaxf(cs[nt][0], cs[nt][1]));
            cm1 = fmaxf(cm1, fmaxf(cs[nt][2], cs[nt][3]));
        }
        cm0 = fmaxf(cm0, __shfl_xor_sync(0xFFFFFFFF, cm0, 1));
        cm0 = fmaxf(cm0, __shfl_xor_sync(0xFFFFFFFF, cm0, 2));
        cm1 = fmaxf(cm1, __shfl_xor_sync(0xFFFFFFFF, cm1, 1));
        cm1 = fmaxf(cm1, __shfl_xor_sync(0xFFFFFFFF, cm1, 2));

        float mn0 = fmaxf(m0r, cm0), mn1 = fmaxf(m1r, cm1);
        float f0 = __expf(m0r - mn0), f1 = __expf(m1r - mn1);
        m0r = mn0; m1r = mn1;

        float rs0 = 0.f, rs1 = 0.f;
        #pragma unroll
        for (int nt = 0; nt < 8; ++nt) {
            cs[nt][0] = __expf(cs[nt][0] - mn0);
            cs[nt][1] = __expf(cs[nt][1] - mn0);
            cs[nt][2] = __expf(cs[nt][2] - mn1);
            cs[nt][3] = __expf(cs[nt][3] - mn1);
            rs0 += cs[nt][0] + cs[nt][1];
            rs1 += cs[nt][2] + cs[nt][3];
        }
        rs0 += __shfl_xor_sync(0xFFFFFFFF, rs0, 1);
        rs0 += __shfl_xor_sync(0xFFFFFFFF, rs0, 2);
        rs1 += __shfl_xor_sync(0xFFFFFFFF, rs1, 1);
        rs1 += __shfl_xor_sync(0xFFFFFFFF, rs1, 2);
        l0r = l0r * f0 + rs0;
        l1r = l1r * f1 + rs1;

        #pragma unroll
        for (int nt = 0; nt < 16; ++nt) {
            co[nt][0] *= f0; co[nt][1] *= f0;
            co[nt][2] *= f1; co[nt][3] *= f1;
        }

        // ---- store P hi/lo to smem ----
        {
            int r0 = lane >> 2;
            uint32_t base0 = (uint32_t)((w * 16 + r0) * VSTR + (lane & 3) * 4);
            #pragma unroll
            for (int nt = 0; nt < 8; ++nt) {
                uint32_t hi, lo;
                split2(cs[nt][0], cs[nt][1], hi, lo);
                uint32_t o0 = base0 + nt * 16;
                *(uint32_t*)(smem + F_PHI + o0) = hi;
                *(uint32_t*)(smem + F_PLO + o0) = lo;
                split2(cs[nt][2], cs[nt][3], hi, lo);
                uint32_t o1 = o0 + 8 * VSTR;
                *(uint32_t*)(smem + F_PHI + o1) = hi;
                *(uint32_t*)(smem + F_PLO + o1) = lo;
            }
        }
        __syncthreads();

        // ---- O += P @ Vc ----
        #pragma unroll
        for (int ks = 0; ks < 4; ++ks) {
            uint32_t ah[4], al[4];
            uint32_t ad = sm + pa_off + (uint32_t)(ks * 32);
            ldmx4(ah[0], ah[1], ah[2], ah[3], ad + F_PHI);
            ldmx4(al[0], al[1], al[2], al[3], ad + F_PLO);
            #pragma unroll
            for (int np = 0; np < 8; ++np) {
                uint32_t bd = sm + vb_base + (uint32_t)(np * 16 * VSTR + ks * 32);
                uint32_t bh[2][2], bl[2][2];
                ldmx4(bh[0][0], bh[0][1], bh[1][0], bh[1][1], bd + F_VHI);
                ldmx4(bl[0][0], bl[0][1], bl[1][0], bl[1][1], bd + F_VLO);
                #pragma unroll
                for (int q = 0; q < 2; ++q) {
                    mma16816(co[np * 2 + q], ah, bh[q]);
                    mma16816(co[np * 2 + q], ah, bl[q]);
                    mma16816(co[np * 2 + q], al, bh[q]);
                }
            }
        }
        __syncthreads();

        // ---- store prefetched next K/V chunk into smem ----
        if (ch + 1 < nch) {
            #pragma unroll
            for (int i = 0; i < 4; ++i) {
                int kr = krow + i * 16;
                uint32_t koff = (uint32_t)(kr * KSTR + kc16 * 16);
                *(uint4*)(smem + F_KHI + koff) = pkh[i];
                *(uint4*)(smem + F_KLO + koff) = pkl[i];
                int vr = vrow + i * 32;
                uint32_t voff = (uint32_t)(vr * VSTR + vc16 * 16);
                *(uint4*)(smem + F_VHI + voff) = pvh[i];
                *(uint4*)(smem + F_VLO + voff) = pvl[i];
            }
            __syncthreads();
        }
    }

    float inv0 = 1.0f / l0r, inv1 = 1.0f / l1r;
    int r0 = lane >> 2;
    #pragma unroll
    for (int nt = 0; nt < 16; ++nt) {
        int row = m0 + w * 16 + r0;
        int col = nt * 8 + (lane & 3) * 2;
        float* p0 = g_ctx + (size_t)(b * NN + row) * (HH * HD) + h * HD + col;
        float* p1 = g_ctx + (size_t)(b * NN + row + 8) * (HH * HD) + h * HD + col;
        *(float2*)p0 = make_float2(co[nt][0] * inv0, co[nt][1] * inv0);
        *(float2*)p1 = make_float2(co[nt][2] * inv1, co[nt][3] * inv1);
    }
}

// ---------------------------------------------------------------------------
// Transposes (weights, fp32 — unchanged)
// ---------------------------------------------------------------------------
__global__ void transpose_f32(const float* __restrict__ src, float* __restrict__ dst,
                              int R, int C)
{
    __shared__ float tile[32][33];
    int c0 = blockIdx.x * 32, r0 = blockIdx.y * 32;
    int tx = threadIdx.x, ty = threadIdx.y;
    #pragma unroll
    for (int i = ty; i < 32; i += 8)
        tile[i][tx] = src[(size_t)(r0 + i) * C + c0 + tx];
    __syncthreads();
    #pragma unroll
    for (int i = ty; i < 32; i += 8)
        dst[(size_t)(c0 + i) * R + r0 + tx] = tile[tx][i];
}

// V: [b][n][hkv][hd] (inside g_QKV, fp32) -> Vt [b][hkv][hd][n] bf16 hi/lo
__global__ void transpose_v_split()
{
    __shared__ float tile[32][33];
    int z = blockIdx.z, b = z / HKV, hkv = z % HKV;
    int n0 = blockIdx.x * 32, d0 = blockIdx.y * 32;
    int tx = threadIdx.x, ty = threadIdx.y;
    #pragma unroll
    for (int i = ty; i < 32; i += 8)
        tile[i][tx] = g_QKV[(size_t)(b * NN + n0 + i) * QKVW + VOFF + hkv * HD + d0 + tx];
    __syncthreads();
    size_t base = (size_t)(b * HKV + hkv) * HD * NN;
    #pragma unroll
    for (int i = ty; i < 32; i += 8) {
        float v = tile[tx][i];
        __nv_bfloat16 h, l;
        split1(v, h, l);
        size_t off = base + (size_t)(d0 + i) * NN + n0 + tx;
        g_Vth[off] = h; g_Vtl[off] = l;
    }
}

// ---------------------------------------------------------------------------
// RoPE + split: g_QKV(fp32) -> Qh/Ql, Kh/Kl
// ---------------------------------------------------------------------------
__global__ void rope_split(const float* __restrict__ cosb,
                           const float* __restrict__ sinb)
{
    int idx = blockIdx.x * blockDim.x + threadIdx.x;
    const int NQ = BB * NN * HH * (HD / 2);
    const int NK = BB * NN * HKV * (HD / 2);
    if (idx < NQ) {
        int i  = idx & 63;
        int h  = (idx >> 6) % HH;
        int bn = idx / (64 * HH);
        int n  = bn % NN;
        float cc = cosb[n * 64 + i], ss = sinb[n * 64 + i];
        const float* q = g_QKV + (size_t)bn * QKVW + h * HD;
        float t1 = q[i], t2 = q[i + 64];
        float r1 = t1 * cc + t2 * ss;
        float r2 = t2 * cc - t1 * ss;
        size_t o = ((size_t)bn * HH + h) * HD;
        __nv_bfloat16 h1, l1, h2, l2;
        split1(r1, h1, l1); split1(r2, h2, l2);
        g_Qh[o + i] = h1; g_Ql[o + i] = l1;
        g_Qh[o + i + 64] = h2; g_Ql[o + i + 64] = l2;
    } else {
        idx -= NQ;
        if (idx < NK) {
            int i  = idx & 63;
            int hk = (idx >> 6) % HKV;
            int bn = idx / (64 * HKV);
            int n  = bn % NN;
            float cc = cosb[n * 64 + i], ss = sinb[n * 64 + i];
            const float* k = g_QKV + (size_t)bn * QKVW + KOFF + hk * HD;
            float t1 = k[i], t2 = k[i + 64];
            float r1 = t1 * cc + t2 * ss;
            float r2 = t2 * cc - t1 * ss;
            size_t o = ((size_t)bn * HKV + hk) * HD;
            __nv_bfloat16 h1, l1, h2, l2;
            split1(r1, h1, l1); split1(r2, h2, l2);
            g_Kh[o + i] = h1; g_Kl[o + i] = l1;
            g_Kh[o + i + 64] = h2; g_Kl[o + i + 64] = l2;
        }
    }
}

// ---------------------------------------------------------------------------
// Launch
// ---------------------------------------------------------------------------
extern "C" void kernel_launch(void* const* d_in, const int* in_sizes, int n_in,
                              void* d_out, int out_size)
{
    (void)in_sizes; (void)n_in; (void)out_size;

    const float* x    = (const float*)d_in[0];
    const float* cosb = (const float*)d_in[1];
    const float* sinb = (const float*)d_in[2];
    const float* mask = (const float*)d_in[3];
    const float* Wq   = (const float*)d_in[4];
    const float* Wkv  = (const float*)d_in[5];
    const float* Wo   = (const float*)d_in[6];
    const float* bo   = (const float*)d_in[7];
    float* out = (float*)d_out;

    float *pQKV, *pWT, *pWoT, *pCtx;
    cudaGetSymbolAddress((void**)&pQKV, g_QKV);
    cudaGetSymbolAddress((void**)&pWT,  g_WT);
    cudaGetSymbolAddress((void**)&pWoT, g_WoT);
    cudaGetSymbolAddress((void**)&pCtx, g_ctx);

    cudaFuncSetAttribute(gemm_nt_mma, cudaFuncAttributeMaxDynamicSharedMemorySize, SMEM_SZ);
    cudaFuncSetAttribute(flash_attn,  cudaFuncAttributeMaxDynamicSharedMemorySize, F_SZ);

    const int M = BB * NN;   // 4096
    dim3 tb(32, 8);

    // Weight transposes
    transpose_f32<<<dim3(DD / 32, DD / 32), tb>>>(Wq, pWT, DD, DD);
    transpose_f32<<<dim3((2 * HKV * HD) / 32, DD / 32), tb>>>(Wkv, pWT + (size_t)KOFF * DD, DD, 2 * HKV * HD);
    transpose_f32<<<dim3(DD / 32, DD / 32), tb>>>(Wo, pWoT, DD, DD);

    // QKV = x @ [Wq|Wkv]
    gemm_nt_mma<<<dim3(QKVW / 128, M / 128), 512, SMEM_SZ>>>(x, DD, pWT, DD, pQKV, QKVW, DD, nullptr);

    // RoPE + split -> bf16 hi/lo Q, K
    {
        int total = BB * NN * HH * (HD / 2) + BB * NN * HKV * (HD / 2);
        rope_split<<<(total + 255) / 256, 256>>>(cosb, sinb);
    }

    // V transpose + split -> bf16 hi/lo Vt
    transpose_v_split<<<dim3(NN / 32, HD / 32, BB * HKV), tb>>>();

    // fused attention
    flash_attn<<<dim3(1, NN / 128, BB * HH), 256, F_SZ>>>(mask);

    // out = ctx @ Wo + bo
    gemm_nt_mma<<<dim3(DD / 128, M / 128), 512, SMEM_SZ>>>(pCtx, HH * HD, pWoT, DD, out, DD, DD, bo);
}

// round 15
// speedup vs baseline: 1.0050x; 1.0050x over previous
#include <cuda_runtime.h>
#include <cuda_bf16.h>
#include <math.h>
#include <cstdint>

// ---------------------------------------------------------------------------
// Problem constants
// ---------------------------------------------------------------------------
#define BB   2
#define NN   2048
#define DD   2048
#define HH   16
#define HKV  4
#define HD   128
#define GG   (HH / HKV)
#define QKVW (HH * HD + 2 * HKV * HD)     // 3072: Q(2048) | K(512) | V(512)
#define KOFF (HH * HD)                    // 2048
#define VOFF (HH * HD + HKV * HD)         // 2560
#define SCALE 0.08838834764831845f

#define BK 64                  // K-chunk (fp32 elements) for gemm
#define TSTR 144               // gemm smem row stride bytes (128 data + 16 pad)
#define TILE_B (128 * TSTR)    // 18432
#define STAGE_B (4 * TILE_B)   // 73728
#define SMEM_SZ (2 * STAGE_B)  // 147456 (gemm, double buffered)
#define OFF_AHI 0
#define OFF_ALO (TILE_B)
#define OFF_BHI (2 * TILE_B)
#define OFF_BLO (3 * TILE_B)

// flash-attention smem layout (bytes)
#define KSTR 272               // 128 bf16 cols (256B) + 16 pad
#define VSTR 144               // 64 bf16 cols (128B) + 16 pad
#define F_QHI 0
#define F_QLO (F_QHI + 128 * KSTR)
#define F_KHI (F_QLO + 128 * KSTR)
#define F_KLO (F_KHI + 64 * KSTR)
#define F_VHI (F_KLO + 64 * KSTR)
#define F_VLO (F_VHI + 128 * VSTR)
#define F_PHI (F_VLO + 128 * VSTR)
#define F_PLO (F_PHI + 128 * VSTR)
#define F_ST  (F_PLO + 128 * VSTR)    // stats: pmax[2][128] then psum[2][128]
#define F_SZ  (F_ST + 2048)           // 180224

// ---------------------------------------------------------------------------
// Device scratch
// ---------------------------------------------------------------------------
__device__ float g_QKV[(size_t)BB * NN * QKVW];            // 48 MB
__device__ float g_WT [(size_t)QKVW * DD];                 // 24 MB
__device__ float g_WoT[(size_t)DD * DD];                   // 16 MB
__device__ float g_ctx[(size_t)BB * NN * HH * HD];         // 32 MB

// pre-split bf16 hi/lo attention operands (flash only)
__device__ __align__(128) __nv_bfloat16 g_Qh [(size_t)BB * NN * HH * HD];
__device__ __align__(128) __nv_bfloat16 g_Ql [(size_t)BB * NN * HH * HD];
__device__ __align__(128) __nv_bfloat16 g_Kh [(size_t)BB * NN * HKV * HD];
__device__ __align__(128) __nv_bfloat16 g_Kl [(size_t)BB * NN * HKV * HD];
__device__ __align__(128) __nv_bfloat16 g_Vth[(size_t)BB * HKV * HD * NN];
__device__ __align__(128) __nv_bfloat16 g_Vtl[(size_t)BB * HKV * HD * NN];

// ---------------------------------------------------------------------------
// PTX helpers
// ---------------------------------------------------------------------------
__device__ __forceinline__ uint32_t smem_u32(const void* p) {
    uint32_t a;
    asm("{ .reg .u64 t; cvta.to.shared.u64 t, %1; cvt.u32.u64 %0, t; }" : "=r"(a) : "l"(p));
    return a;
}
__device__ __forceinline__ void ldmx4(uint32_t& r0, uint32_t& r1, uint32_t& r2, uint32_t& r3, uint32_t addr) {
    asm volatile("ldmatrix.sync.aligned.m8n8.x4.shared.b16 {%0,%1,%2,%3}, [%4];"
                 : "=r"(r0), "=r"(r1), "=r"(r2), "=r"(r3) : "r"(addr));
}
__device__ __forceinline__ void mma16816(float* c, const uint32_t* a, const uint32_t* b) {
    asm volatile(
        "mma.sync.aligned.m16n8k16.row.col.f32.bf16.bf16.f32 "
        "{%0,%1,%2,%3}, {%4,%5,%6,%7}, {%8,%9}, {%0,%1,%2,%3};"
        : "+f"(c[0]), "+f"(c[1]), "+f"(c[2]), "+f"(c[3])
        : "r"(a[0]), "r"(a[1]), "r"(a[2]), "r"(a[3]), "r"(b[0]), "r"(b[1]));
}

__device__ __forceinline__ void split4(float4 v, uint2& hi, uint2& lo) {
    __nv_bfloat16 hx = __float2bfloat16(v.x), hy = __float2bfloat16(v.y),
                  hz = __float2bfloat16(v.z), hw = __float2bfloat16(v.w);
    __nv_bfloat162 h01 = __halves2bfloat162(hx, hy), h23 = __halves2bfloat162(hz, hw);
    __nv_bfloat16 lx = __float2bfloat16(v.x - __bfloat162float(hx));
    __nv_bfloat16 ly = __float2bfloat16(v.y - __bfloat162float(hy));
    __nv_bfloat16 lz = __float2bfloat16(v.z - __bfloat162float(hz));
    __nv_bfloat16 lw = __float2bfloat16(v.w - __bfloat162float(hw));
    __nv_bfloat162 l01 = __halves2bfloat162(lx, ly), l23 = __halves2bfloat162(lz, lw);
    hi = make_uint2(*(uint32_t*)&h01, *(uint32_t*)&h23);
    lo = make_uint2(*(uint32_t*)&l01, *(uint32_t*)&l23);
}
__device__ __forceinline__ void split2(float a, float b, uint32_t& hi, uint32_t& lo) {
    __nv_bfloat16 ha = __float2bfloat16(a), hb = __float2bfloat16(b);
    __nv_bfloat16 la = __float2bfloat16(a - __bfloat162float(ha));
    __nv_bfloat16 lb = __float2bfloat16(b - __bfloat162float(hb));
    __nv_bfloat162 hp = __halves2bfloat162(ha, hb), lp = __halves2bfloat162(la, lb);
    hi = *(uint32_t*)&hp; lo = *(uint32_t*)&lp;
}
__device__ __forceinline__ void split1(float v, __nv_bfloat16& h, __nv_bfloat16& l) {
    h = __float2bfloat16(v);
    l = __float2bfloat16(v - __bfloat162float(h));
}

// gemm stage store — BK=64, 512 threads: 4 float4 per tile per thread
__device__ __forceinline__ void store_stage(char* sb, int t, const float4* pa, const float4* pb) {
    #pragma unroll
    for (int i = 0; i < 4; ++i) {
        int idx = t + i * 512, row = idx >> 4, c4 = idx & 15;
        uint32_t off = (uint32_t)(row * TSTR + c4 * 8);
        uint2 hi, lo;
        split4(pa[i], hi, lo);
        *(uint2*)(sb + OFF_AHI + off) = hi;
        *(uint2*)(sb + OFF_ALO + off) = lo;
        split4(pb[i], hi, lo);
        *(uint2*)(sb + OFF_BHI + off) = hi;
        *(uint2*)(sb + OFF_BLO + off) = lo;
    }
}

// ---------------------------------------------------------------------------
// GEMM mainloop — unchanged from R11 (512 thr, 16 warps, BK=64, double buffer)
// ---------------------------------------------------------------------------
__device__ __forceinline__ void mma_mainloop(
    const float* __restrict__ A, int lda,
    const float* __restrict__ B, int ldb, int K,
    float c[2][4][4])
{
    extern __shared__ __align__(16) char smem[];
    const int t    = threadIdx.x;
    const int lane = t & 31;
    const int warp = t >> 5;
    const int wm   = warp >> 2;
    const int wn   = warp & 3;
    const uint32_t sm = smem_u32(smem);

    const uint32_t a_off = (uint32_t)((wm * 32 + (lane & 15)) * TSTR + (lane >> 4) * 16);
    const uint32_t b_off = (uint32_t)(OFF_BHI + (wn * 32 + ((lane >> 4) * 8) + (lane & 7)) * TSTR + ((lane >> 3) & 1) * 16);

    float4 pa[4], pb[4];
    const int nch = K / BK;

    #pragma unroll
    for (int i = 0; i < 4; ++i) {
        int idx = t + i * 512, row = idx >> 4, c4 = idx & 15;
        pa[i] = *(const float4*)(A + (size_t)row * lda + c4 * 4);
        pb[i] = *(const float4*)(B + (size_t)row * ldb + c4 * 4);
    }
    store_stage(smem, t, pa, pb);
    __syncthreads();

    uint32_t buf = 0;
    for (int ch = 0; ch < nch; ++ch) {
        if (ch + 1 < nch) {
            const int k0 = (ch + 1) * BK;
            #pragma unroll
            for (int i = 0; i < 4; ++i) {
                int idx = t + i * 512, row = idx >> 4, c4 = idx & 15;
                pa[i] = *(const float4*)(A + (size_t)row * lda + k0 + c4 * 4);
                pb[i] = *(const float4*)(B + (size_t)row * ldb + k0 + c4 * 4);
            }
        }
        const uint32_t sb = sm + buf * STAGE_B;
        #pragma unroll
        for (int ks = 0; ks < 4; ++ks) {
            uint32_t ah[2][4], al[2][4], bh[4][2], bl[4][2];
            #pragma unroll
            for (int mt = 0; mt < 2; ++mt) {
                uint32_t ad = sb + a_off + (uint32_t)(mt * 16 * TSTR + ks * 32);
                ldmx4(ah[mt][0], ah[mt][1], ah[mt][2], ah[mt][3], ad + OFF_AHI);
                ldmx4(al[mt][0], al[mt][1], al[mt][2], al[mt][3], ad + OFF_ALO);
            }
            #pragma unroll
            for (int np = 0; np < 2; ++np) {
                uint32_t ad = sb + b_off + (uint32_t)(np * 16 * TSTR + ks * 32);
                ldmx4(bh[np * 2][0], bh[np * 2][1], bh[np * 2 + 1][0], bh[np * 2 + 1][1], ad);
                ldmx4(bl[np * 2][0], bl[np * 2][1], bl[np * 2 + 1][0], bl[np * 2 + 1][1], ad + TILE_B);
            }
            #pragma unroll
            for (int mt = 0; mt < 2; ++mt)
                #pragma unroll
                for (int nt = 0; nt < 4; ++nt) {
                    mma16816(c[mt][nt], ah[mt], bh[nt]);
                    mma16816(c[mt][nt], ah[mt], bl[nt]);
                    mma16816(c[mt][nt], al[mt], bh[nt]);
                }
        }
        if (ch + 1 < nch)
            store_stage(smem + (buf ^ 1) * STAGE_B, t, pa, pb);
        __syncthreads();
        buf ^= 1;
    }
}

#define ACC_INIT4(c) \
    _Pragma("unroll") for (int mt = 0; mt < 2; ++mt) \
    _Pragma("unroll") for (int nt = 0; nt < 4; ++nt) \
    _Pragma("unroll") for (int i = 0; i < 4; ++i) c[mt][nt][i] = 0.f

// ---------------------------------------------------------------------------
// Generic NT GEMM (unchanged from R11)
// ---------------------------------------------------------------------------
__global__ __launch_bounds__(512) void gemm_nt_mma(
    const float* __restrict__ A, int lda,
    const float* __restrict__ B, int ldb,
    float* __restrict__ C, int ldc, int K,
    const float* __restrict__ bias)
{
    const int m0 = blockIdx.y * 128, n0 = blockIdx.x * 128;
    float c[2][4][4];
    ACC_INIT4(c);

    mma_mainloop(A + (size_t)m0 * lda, lda, B + (size_t)n0 * ldb, ldb, K, c);

    const int lane = threadIdx.x & 31, warp = threadIdx.x >> 5;
    const int rb = m0 + (warp >> 2) * 32 + (lane >> 2);
    const int cb = n0 + (warp & 3) * 32 + (lane & 3) * 2;
    #pragma unroll
    for (int mt = 0; mt < 2; ++mt)
        #pragma unroll
        for (int nt = 0; nt < 4; ++nt) {
            int row = rb + mt * 16, col = cb + nt * 8;
            float b0 = bias ? bias[col] : 0.f, b1 = bias ? bias[col + 1] : 0.f;
            *(float2*)(C + (size_t)row * ldc + col)       = make_float2(c[mt][nt][0] + b0, c[mt][nt][1] + b1);
            *(float2*)(C + (size_t)(row + 8) * ldc + col) = make_float2(c[mt][nt][2] + b0, c[mt][nt][3] + b1);
        }
}

// ---------------------------------------------------------------------------
// Fused flash attention — 512 threads, 16 warps: warp (wq, wk).
// wq in [0,8): 16 q-rows. wk in [0,2): splits 64-key chunk for QK (32 keys
// each) and 128 hd-cols for PV (64 each). Row softmax stats are combined
// across the wk-pair through a smem stats region (GENERIC-pointer access —
// the R14 crash was dereferencing a cvta.to.shared address as generic).
// Full 3-MMA hi/lo.
// ---------------------------------------------------------------------------
__global__ __launch_bounds__(512) void flash_attn(const float* __restrict__ mask)
{
    extern __shared__ __align__(16) char smem[];
    const int z = blockIdx.z, b = z / HH, h = z % HH, hkv = h % HKV;
    const int m0 = blockIdx.y * 128;
    const int t = threadIdx.x, lane = t & 31, w = t >> 5;
    const int wq = w >> 1, wk = w & 1;
    const uint32_t sm = smem_u32(smem);

    // ---- load Q tile [128 x HD] bf16 hi/lo (once) ----
    {
        const __nv_bfloat16* Qh = g_Qh + ((size_t)(b * NN + m0) * HH + h) * HD;
        const __nv_bfloat16* Ql = g_Ql + ((size_t)(b * NN + m0) * HH + h) * HD;
        #pragma unroll
        for (int i = 0; i < 4; ++i) {
            int idx = t + i * 512, row = idx >> 4, c16 = idx & 15;
            uint32_t off = (uint32_t)(row * KSTR + c16 * 16);
            size_t g = (size_t)row * (HH * HD) + c16 * 8;
            *(uint4*)(smem + F_QHI + off) = *(const uint4*)(Qh + g);
            *(uint4*)(smem + F_QLO + off) = *(const uint4*)(Ql + g);
        }
    }

    float co[8][4];
    #pragma unroll
    for (int nt = 0; nt < 8; ++nt)
        #pragma unroll
        for (int i = 0; i < 4; ++i) co[nt][i] = 0.f;
    float m0r = -INFINITY, m1r = -INFINITY;
    float l0r = 0.f, l1r = 0.f;

    const uint32_t qa_off  = (uint32_t)((wq * 16 + (lane & 15)) * KSTR + (lane >> 4) * 16);
    const uint32_t kb_base = (uint32_t)((wk * 32 + (lane >> 4) * 8 + (lane & 7)) * KSTR + ((lane >> 3) & 1) * 16);
    const uint32_t pa_off  = (uint32_t)((wq * 16 + (lane & 15)) * VSTR + (lane >> 4) * 16);
    const uint32_t vb_base = (uint32_t)((wk * 64 + (lane >> 4) * 8 + (lane & 7)) * VSTR + ((lane >> 3) & 1) * 16);

    const int r0 = lane >> 2;           // row-in-16 for stats / P-store
    const int row0 = wq * 16 + r0;      // 0..127 (and +8)
    char* st_max = smem + F_ST;         // generic pointers (FIX)
    char* st_sum = smem + F_ST + 1024;

    __syncthreads();

    for (int ch = 0; ch < NN / 64; ++ch) {
        const int n0 = ch * 64;
        // ---- load K chunk [64 x HD] bf16 hi/lo ----
        {
            const __nv_bfloat16* Kh = g_Kh + ((size_t)(b * NN + n0) * HKV + hkv) * HD;
            const __nv_bfloat16* Kl = g_Kl + ((size_t)(b * NN + n0) * HKV + hkv) * HD;
            #pragma unroll
            for (int i = 0; i < 2; ++i) {
                int idx = t + i * 512, row = idx >> 4, c16 = idx & 15;
                uint32_t off = (uint32_t)(row * KSTR + c16 * 16);
                size_t g = (size_t)row * (HKV * HD) + c16 * 8;
                *(uint4*)(smem + F_KHI + off) = *(const uint4*)(Kh + g);
                *(uint4*)(smem + F_KLO + off) = *(const uint4*)(Kl + g);
            }
        }
        // ---- load V chunk [128(hd) x 64(n)] bf16 hi/lo ----
        {
            const __nv_bfloat16* Vh = g_Vth + (size_t)(b * HKV + hkv) * HD * NN + n0;
            const __nv_bfloat16* Vl = g_Vtl + (size_t)(b * HKV + hkv) * HD * NN + n0;
            #pragma unroll
            for (int i = 0; i < 2; ++i) {
                int idx = t + i * 512, row = idx >> 3, c16 = idx & 7;
                uint32_t off = (uint32_t)(row * VSTR + c16 * 16);
                size_t g = (size_t)row * NN + c16 * 8;
                *(uint4*)(smem + F_VHI + off) = *(const uint4*)(Vh + g);
                *(uint4*)(smem + F_VLO + off) = *(const uint4*)(Vl + g);
            }
        }
        __syncthreads();

        // ---- S = Q @ Kc^T : warp computes 16 x 32 (its wk key-half) ----
        float cs[4][4];
        #pragma unroll
        for (int nt = 0; nt < 4; ++nt)
            #pragma unroll
            for (int i = 0; i < 4; ++i) cs[nt][i] = 0.f;

        #pragma unroll
        for (int ks = 0; ks < 8; ++ks) {
            uint32_t ah[4], al[4];
            uint32_t ad = sm + qa_off + (uint32_t)(ks * 32);
            ldmx4(ah[0], ah[1], ah[2], ah[3], ad + F_QHI);
            ldmx4(al[0], al[1], al[2], al[3], ad + F_QLO);
            #pragma unroll
            for (int np = 0; np < 2; ++np) {
                uint32_t bd = sm + kb_base + (uint32_t)(np * 16 * KSTR + ks * 32);
                uint32_t bh[2][2], bl[2][2];
                ldmx4(bh[0][0], bh[0][1], bh[1][0], bh[1][1], bd + F_KHI);
                ldmx4(bl[0][0], bl[0][1], bl[1][0], bl[1][1], bd + F_KLO);
                #pragma unroll
                for (int q = 0; q < 2; ++q) {
                    mma16816(cs[np * 2 + q], ah, bh[q]);
                    mma16816(cs[np * 2 + q], ah, bl[q]);
                    mma16816(cs[np * 2 + q], al, bh[q]);
                }
            }
        }

        // ---- scale + mask bias (cols n0 + wk*32 + ...) ----
        #pragma unroll
        for (int nt = 0; nt < 4; ++nt) {
            int col = n0 + wk * 32 + nt * 8 + (lane & 3) * 2;
            float mb0 = (1.0f - mask[b * NN + col]) * -1e9f;
            float mb1 = (1.0f - mask[b * NN + col + 1]) * -1e9f;
            cs[nt][0] = cs[nt][0] * SCALE + mb0;
            cs[nt][1] = cs[nt][1] * SCALE + mb1;
            cs[nt][2] = cs[nt][2] * SCALE + mb0;
            cs[nt][3] = cs[nt][3] * SCALE + mb1;
        }

        // ---- partial row max over this warp's 32 keys ----
        float cm0 = -INFINITY, cm1 = -INFINITY;
        #pragma unroll
        for (int nt = 0; nt < 4; ++nt) {
            cm0 = fmaxf(cm0, fmaxf(cs[nt][0], cs[nt][1]));
            cm1 = fmaxf(cm1, fmaxf(cs[nt][2], cs[nt][3]));
        }
        cm0 = fmaxf(cm0, __shfl_xor_sync(0xFFFFFFFF, cm0, 1));
        cm0 = fmaxf(cm0, __shfl_xor_sync(0xFFFFFFFF, cm0, 2));
        cm1 = fmaxf(cm1, __shfl_xor_sync(0xFFFFFFFF, cm1, 1));
        cm1 = fmaxf(cm1, __shfl_xor_sync(0xFFFFFFFF, cm1, 2));

        if ((lane & 3) == 0) {
            *(float*)(st_max + (wk * 128 + row0) * 4)     = cm0;
            *(float*)(st_max + (wk * 128 + row0 + 8) * 4) = cm1;
        }
        __syncthreads();
        cm0 = fmaxf(cm0, *(float*)(st_max + ((wk ^ 1) * 128 + row0) * 4));
        cm1 = fmaxf(cm1, *(float*)(st_max + ((wk ^ 1) * 128 + row0 + 8) * 4));

        float mn0 = fmaxf(m0r, cm0), mn1 = fmaxf(m1r, cm1);
        float f0 = __expf(m0r - mn0), f1 = __expf(m1r - mn1);
        m0r = mn0; m1r = mn1;

        // rescale O (f identical across the wk-pair)
        #pragma unroll
        for (int nt = 0; nt < 8; ++nt) {
            co[nt][0] *= f0; co[nt][1] *= f0;
            co[nt][2] *= f1; co[nt][3] *= f1;
        }

        // ---- exponentiate + partial row sums ----
        float rs0 = 0.f, rs1 = 0.f;
        #pragma unroll
        for (int nt = 0; nt < 4; ++nt) {
            cs[nt][0] = __expf(cs[nt][0] - mn0);
            cs[nt][1] = __expf(cs[nt][1] - mn0);
            cs[nt][2] = __expf(cs[nt][2] - mn1);
            cs[nt][3] = __expf(cs[nt][3] - mn1);
            rs0 += cs[nt][0] + cs[nt][1];
            rs1 += cs[nt][2] + cs[nt][3];
        }
        rs0 += __shfl_xor_sync(0xFFFFFFFF, rs0, 1);
        rs0 += __shfl_xor_sync(0xFFFFFFFF, rs0, 2);
        rs1 += __shfl_xor_sync(0xFFFFFFFF, rs1, 1);
        rs1 += __shfl_xor_sync(0xFFFFFFFF, rs1, 2);

        if ((lane & 3) == 0) {
            *(float*)(st_sum + (wk * 128 + row0) * 4)     = rs0;
            *(float*)(st_sum + (wk * 128 + row0 + 8) * 4) = rs1;
        }

        // ---- store P hi/lo to smem (rows wq*16.., key cols wk*32..) ----
        {
            uint32_t base0 = (uint32_t)((wq * 16 + r0) * VSTR + wk * 64 + (lane & 3) * 4);
            #pragma unroll
            for (int nt = 0; nt < 4; ++nt) {
                uint32_t hi, lo;
                split2(cs[nt][0], cs[nt][1], hi, lo);
                uint32_t o0 = base0 + nt * 16;
                *(uint32_t*)(smem + F_PHI + o0) = hi;
                *(uint32_t*)(smem + F_PLO + o0) = lo;
                split2(cs[nt][2], cs[nt][3], hi, lo);
                uint32_t o1 = o0 + 8 * VSTR;
                *(uint32_t*)(smem + F_PHI + o1) = hi;
                *(uint32_t*)(smem + F_PLO + o1) = lo;
            }
        }
        __syncthreads();

        // combine row sums across the wk-pair
        rs0 += *(float*)(st_sum + ((wk ^ 1) * 128 + row0) * 4);
        rs1 += *(float*)(st_sum + ((wk ^ 1) * 128 + row0 + 8) * 4);
        l0r = l0r * f0 + rs0;
        l1r = l1r * f1 + rs1;

        // ---- O += P @ Vc : warp covers hd cols [wk*64, wk*64+64) ----
        #pragma unroll
        for (int ks = 0; ks < 4; ++ks) {
            uint32_t ah[4], al[4];
            uint32_t ad = sm + pa_off + (uint32_t)(ks * 32);
            ldmx4(ah[0], ah[1], ah[2], ah[3], ad + F_PHI);
            ldmx4(al[0], al[1], al[2], al[3], ad + F_PLO);
            #pragma unroll
            for (int np = 0; np < 4; ++np) {
                uint32_t bd = sm + vb_base + (uint32_t)(np * 16 * VSTR + ks * 32);
                uint32_t bh[2][2], bl[2][2];
                ldmx4(bh[0][0], bh[0][1], bh[1][0], bh[1][1], bd + F_VHI);
                ldmx4(bl[0][0], bl[0][1], bl[1][0], bl[1][1], bd + F_VLO);
                #pragma unroll
                for (int q = 0; q < 2; ++q) {
                    mma16816(co[np * 2 + q], ah, bh[q]);
                    mma16816(co[np * 2 + q], ah, bl[q]);
                    mma16816(co[np * 2 + q], al, bh[q]);
                }
            }
        }
        __syncthreads();
    }

    // ---- epilogue: normalize, write hd cols [wk*64, wk*64+64) ----
    float inv0 = 1.0f / l0r, inv1 = 1.0f / l1r;
    #pragma unroll
    for (int nt = 0; nt < 8; ++nt) {
        int row = m0 + wq * 16 + r0;
        int col = wk * 64 + nt * 8 + (lane & 3) * 2;
        float* p0 = g_ctx + (size_t)(b * NN + row) * (HH * HD) + h * HD + col;
        float* p1 = g_ctx + (size_t)(b * NN + row + 8) * (HH * HD) + h * HD + col;
        *(float2*)p0 = make_float2(co[nt][0] * inv0, co[nt][1] * inv0);
        *(float2*)p1 = make_float2(co[nt][2] * inv1, co[nt][3] * inv1);
    }
}

// ---------------------------------------------------------------------------
// Transposes (weights, fp32 — unchanged)
// ---------------------------------------------------------------------------
__global__ void transpose_f32(const float* __restrict__ src, float* __restrict__ dst,
                              int R, int C)
{
    __shared__ float tile[32][33];
    int c0 = blockIdx.x * 32, r0 = blockIdx.y * 32;
    int tx = threadIdx.x, ty = threadIdx.y;
    #pragma unroll
    for (int i = ty; i < 32; i += 8)
        tile[i][tx] = src[(size_t)(r0 + i) * C + c0 + tx];
    __syncthreads();
    #pragma unroll
    for (int i = ty; i < 32; i += 8)
        dst[(size_t)(c0 + i) * R + r0 + tx] = tile[tx][i];
}

// V: [b][n][hkv][hd] (inside g_QKV, fp32) -> Vt [b][hkv][hd][n] bf16 hi/lo
__global__ void transpose_v_split()
{
    __shared__ float tile[32][33];
    int z = blockIdx.z, b = z / HKV, hkv = z % HKV;
    int n0 = blockIdx.x * 32, d0 = blockIdx.y * 32;
    int tx = threadIdx.x, ty = threadIdx.y;
    #pragma unroll
    for (int i = ty; i < 32; i += 8)
        tile[i][tx] = g_QKV[(size_t)(b * NN + n0 + i) * QKVW + VOFF + hkv * HD + d0 + tx];
    __syncthreads();
    size_t base = (size_t)(b * HKV + hkv) * HD * NN;
    #pragma unroll
    for (int i = ty; i < 32; i += 8) {
        float v = tile[tx][i];
        __nv_bfloat16 h, l;
        split1(v, h, l);
        size_t off = base + (size_t)(d0 + i) * NN + n0 + tx;
        g_Vth[off] = h; g_Vtl[off] = l;
    }
}

// ---------------------------------------------------------------------------
// RoPE + split: g_QKV(fp32) -> Qh/Ql, Kh/Kl
// ---------------------------------------------------------------------------
__global__ void rope_split(const float* __restrict__ cosb,
                           const float* __restrict__ sinb)
{
    int idx = blockIdx.x * blockDim.x + threadIdx.x;
    const int NQ = BB * NN * HH * (HD / 2);
    const int NK = BB * NN * HKV * (HD / 2);
    if (idx < NQ) {
        int i  = idx & 63;
        int h  = (idx >> 6) % HH;
        int bn = idx / (64 * HH);
        int n  = bn % NN;
        float cc = cosb[n * 64 + i], ss = sinb[n * 64 + i];
        const float* q = g_QKV + (size_t)bn * QKVW + h * HD;
        float t1 = q[i], t2 = q[i + 64];
        float r1 = t1 * cc + t2 * ss;
        float r2 = t2 * cc - t1 * ss;
        size_t o = ((size_t)bn * HH + h) * HD;
        __nv_bfloat16 h1, l1, h2, l2;
        split1(r1, h1, l1); split1(r2, h2, l2);
        g_Qh[o + i] = h1; g_Ql[o + i] = l1;
        g_Qh[o + i + 64] = h2; g_Ql[o + i + 64] = l2;
    } else {
        idx -= NQ;
        if (idx < NK) {
            int i  = idx & 63;
            int hk = (idx >> 6) % HKV;
            int bn = idx / (64 * HKV);
            int n  = bn % NN;
            float cc = cosb[n * 64 + i], ss = sinb[n * 64 + i];
            const float* k = g_QKV + (size_t)bn * QKVW + KOFF + hk * HD;
            float t1 = k[i], t2 = k[i + 64];
            float r1 = t1 * cc + t2 * ss;
            float r2 = t2 * cc - t1 * ss;
            size_t o = ((size_t)bn * HKV + hk) * HD;
            __nv_bfloat16 h1, l1, h2, l2;
            split1(r1, h1, l1); split1(r2, h2, l2);
            g_Kh[o + i] = h1; g_Kl[o + i] = l1;
            g_Kh[o + i + 64] = h2; g_Kl[o + i + 64] = l2;
        }
    }
}

// ---------------------------------------------------------------------------
// Launch
// ---------------------------------------------------------------------------
extern "C" void kernel_launch(void* const* d_in, const int* in_sizes, int n_in,
                              void* d_out, int out_size)
{
    (void)in_sizes; (void)n_in; (void)out_size;

    const float* x    = (const float*)d_in[0];
    const float* cosb = (const float*)d_in[1];
    const float* sinb = (const float*)d_in[2];
    const float* mask = (const float*)d_in[3];
    const float* Wq   = (const float*)d_in[4];
    const float* Wkv  = (const float*)d_in[5];
    const float* Wo   = (const float*)d_in[6];
    const float* bo   = (const float*)d_in[7];
    float* out = (float*)d_out;

    float *pQKV, *pWT, *pWoT, *pCtx;
    cudaGetSymbolAddress((void**)&pQKV, g_QKV);
    cudaGetSymbolAddress((void**)&pWT,  g_WT);
    cudaGetSymbolAddress((void**)&pWoT, g_WoT);
    cudaGetSymbolAddress((void**)&pCtx, g_ctx);

    cudaFuncSetAttribute(gemm_nt_mma, cudaFuncAttributeMaxDynamicSharedMemorySize, SMEM_SZ);
    cudaFuncSetAttribute(flash_attn,  cudaFuncAttributeMaxDynamicSharedMemorySize, F_SZ);

    const int M = BB * NN;   // 4096
    dim3 tb(32, 8);

    // Weight transposes
    transpose_f32<<<dim3(DD / 32, DD / 32), tb>>>(Wq, pWT, DD, DD);
    transpose_f32<<<dim3((2 * HKV * HD) / 32, DD / 32), tb>>>(Wkv, pWT + (size_t)KOFF * DD, DD, 2 * HKV * HD);
    transpose_f32<<<dim3(DD / 32, DD / 32), tb>>>(Wo, pWoT, DD, DD);

    // QKV = x @ [Wq|Wkv]
    gemm_nt_mma<<<dim3(QKVW / 128, M / 128), 512, SMEM_SZ>>>(x, DD, pWT, DD, pQKV, QKVW, DD, nullptr);

    // RoPE + split -> bf16 hi/lo Q, K
    {
        int total = BB * NN * HH * (HD / 2) + BB * NN * HKV * (HD / 2);
        rope_split<<<(total + 255) / 256, 256>>>(cosb, sinb);
    }

    // V transpose + split -> bf16 hi/lo Vt
    transpose_v_split<<<dim3(NN / 32, HD / 32, BB * HKV), tb>>>();

    // fused attention (512 threads)
    flash_attn<<<dim3(1, NN / 128, BB * HH), 512, F_SZ>>>(mask);

    // out = ctx @ Wo + bo
    gemm_nt_mma<<<dim3(DD / 128, M / 128), 512, SMEM_SZ>>>(pCtx, HH * HD, pWoT, DD, out, DD, DD, bo);
}

// round 16
// speedup vs baseline: 1.0072x; 1.0021x over previous
#include <cuda_runtime.h>
#include <cuda_bf16.h>
#include <math.h>
#include <cstdint>

// ---------------------------------------------------------------------------
// Problem constants
// ---------------------------------------------------------------------------
#define BB   2
#define NN   2048
#define DD   2048
#define HH   16
#define HKV  4
#define HD   128
#define QKVW (HH * HD + 2 * HKV * HD)     // 3072
#define KOFF (HH * HD)                    // 2048
#define SCALE 0.08838834764831845f

#define BK 64                  // K-chunk for gemm
#define TSTR 144               // gemm smem row stride bytes
#define TILE_B (128 * TSTR)
#define STAGE_B (4 * TILE_B)
#define SMEM_SZ (2 * STAGE_B)  // 147456
#define OFF_AHI 0
#define OFF_ALO (TILE_B)
#define OFF_BHI (2 * TILE_B)
#define OFF_BLO (3 * TILE_B)

// flash-attention smem layout (R11)
#define KSTR 272
#define VSTR 144
#define F_QHI 0
#define F_QLO (F_QHI + 128 * KSTR)
#define F_KHI (F_QLO + 128 * KSTR)
#define F_KLO (F_KHI + 64 * KSTR)
#define F_VHI (F_KLO + 64 * KSTR)
#define F_VLO (F_VHI + 128 * VSTR)
#define F_PHI (F_VLO + 128 * VSTR)
#define F_PLO (F_PHI + 128 * VSTR)
#define F_SZ  (F_PLO + 128 * VSTR)    // 178176

// epilogue staging stride (floats)
#define ESTR 132

// ---------------------------------------------------------------------------
// Device scratch
// ---------------------------------------------------------------------------
__device__ float g_WT [(size_t)QKVW * DD];                 // 24 MB
__device__ float g_WoT[(size_t)DD * DD];                   // 16 MB
__device__ float g_ctx[(size_t)BB * NN * HH * HD];         // 32 MB

__device__ __align__(128) __nv_bfloat16 g_Qh [(size_t)BB * NN * HH * HD];
__device__ __align__(128) __nv_bfloat16 g_Ql [(size_t)BB * NN * HH * HD];
__device__ __align__(128) __nv_bfloat16 g_Kh [(size_t)BB * NN * HKV * HD];
__device__ __align__(128) __nv_bfloat16 g_Kl [(size_t)BB * NN * HKV * HD];
__device__ __align__(128) __nv_bfloat16 g_Vth[(size_t)BB * HKV * HD * NN];
__device__ __align__(128) __nv_bfloat16 g_Vtl[(size_t)BB * HKV * HD * NN];

// ---------------------------------------------------------------------------
// PTX helpers
// ---------------------------------------------------------------------------
__device__ __forceinline__ uint32_t smem_u32(const void* p) {
    uint32_t a;
    asm("{ .reg .u64 t; cvta.to.shared.u64 t, %1; cvt.u32.u64 %0, t; }" : "=r"(a) : "l"(p));
    return a;
}
__device__ __forceinline__ void ldmx4(uint32_t& r0, uint32_t& r1, uint32_t& r2, uint32_t& r3, uint32_t addr) {
    asm volatile("ldmatrix.sync.aligned.m8n8.x4.shared.b16 {%0,%1,%2,%3}, [%4];"
                 : "=r"(r0), "=r"(r1), "=r"(r2), "=r"(r3) : "r"(addr));
}
__device__ __forceinline__ void mma16816(float* c, const uint32_t* a, const uint32_t* b) {
    asm volatile(
        "mma.sync.aligned.m16n8k16.row.col.f32.bf16.bf16.f32 "
        "{%0,%1,%2,%3}, {%4,%5,%6,%7}, {%8,%9}, {%0,%1,%2,%3};"
        : "+f"(c[0]), "+f"(c[1]), "+f"(c[2]), "+f"(c[3])
        : "r"(a[0]), "r"(a[1]), "r"(a[2]), "r"(a[3]), "r"(b[0]), "r"(b[1]));
}

__device__ __forceinline__ void split4(float4 v, uint2& hi, uint2& lo) {
    __nv_bfloat16 hx = __float2bfloat16(v.x), hy = __float2bfloat16(v.y),
                  hz = __float2bfloat16(v.z), hw = __float2bfloat16(v.w);
    __nv_bfloat162 h01 = __halves2bfloat162(hx, hy), h23 = __halves2bfloat162(hz, hw);
    __nv_bfloat16 lx = __float2bfloat16(v.x - __bfloat162float(hx));
    __nv_bfloat16 ly = __float2bfloat16(v.y - __bfloat162float(hy));
    __nv_bfloat16 lz = __float2bfloat16(v.z - __bfloat162float(hz));
    __nv_bfloat16 lw = __float2bfloat16(v.w - __bfloat162float(hw));
    __nv_bfloat162 l01 = __halves2bfloat162(lx, ly), l23 = __halves2bfloat162(lz, lw);
    hi = make_uint2(*(uint32_t*)&h01, *(uint32_t*)&h23);
    lo = make_uint2(*(uint32_t*)&l01, *(uint32_t*)&l23);
}
__device__ __forceinline__ void split2(float a, float b, uint32_t& hi, uint32_t& lo) {
    __nv_bfloat16 ha = __float2bfloat16(a), hb = __float2bfloat16(b);
    __nv_bfloat16 la = __float2bfloat16(a - __bfloat162float(ha));
    __nv_bfloat16 lb = __float2bfloat16(b - __bfloat162float(hb));
    __nv_bfloat162 hp = __halves2bfloat162(ha, hb), lp = __halves2bfloat162(la, lb);
    hi = *(uint32_t*)&hp; lo = *(uint32_t*)&lp;
}

// gemm stage store — BK=64, 512 threads
__device__ __forceinline__ void store_stage(char* sb, int t, const float4* pa, const float4* pb) {
    #pragma unroll
    for (int i = 0; i < 4; ++i) {
        int idx = t + i * 512, row = idx >> 4, c4 = idx & 15;
        uint32_t off = (uint32_t)(row * TSTR + c4 * 8);
        uint2 hi, lo;
        split4(pa[i], hi, lo);
        *(uint2*)(sb + OFF_AHI + off) = hi;
        *(uint2*)(sb + OFF_ALO + off) = lo;
        split4(pb[i], hi, lo);
        *(uint2*)(sb + OFF_BHI + off) = hi;
        *(uint2*)(sb + OFF_BLO + off) = lo;
    }
}

// ---------------------------------------------------------------------------
// GEMM mainloop — unchanged R11 (512 thr, 16 warps, BK=64, double buffer)
// ---------------------------------------------------------------------------
__device__ __forceinline__ void mma_mainloop(
    const float* __restrict__ A, int lda,
    const float* __restrict__ B, int ldb, int K,
    float c[2][4][4])
{
    extern __shared__ __align__(16) char smem[];
    const int t    = threadIdx.x;
    const int lane = t & 31;
    const int warp = t >> 5;
    const int wm   = warp >> 2;
    const int wn   = warp & 3;
    const uint32_t sm = smem_u32(smem);

    const uint32_t a_off = (uint32_t)((wm * 32 + (lane & 15)) * TSTR + (lane >> 4) * 16);
    const uint32_t b_off = (uint32_t)(OFF_BHI + (wn * 32 + ((lane >> 4) * 8) + (lane & 7)) * TSTR + ((lane >> 3) & 1) * 16);

    float4 pa[4], pb[4];
    const int nch = K / BK;

    #pragma unroll
    for (int i = 0; i < 4; ++i) {
        int idx = t + i * 512, row = idx >> 4, c4 = idx & 15;
        pa[i] = *(const float4*)(A + (size_t)row * lda + c4 * 4);
        pb[i] = *(const float4*)(B + (size_t)row * ldb + c4 * 4);
    }
    store_stage(smem, t, pa, pb);
    __syncthreads();

    uint32_t buf = 0;
    for (int ch = 0; ch < nch; ++ch) {
        if (ch + 1 < nch) {
            const int k0 = (ch + 1) * BK;
            #pragma unroll
            for (int i = 0; i < 4; ++i) {
                int idx = t + i * 512, row = idx >> 4, c4 = idx & 15;
                pa[i] = *(const float4*)(A + (size_t)row * lda + k0 + c4 * 4);
                pb[i] = *(const float4*)(B + (size_t)row * ldb + k0 + c4 * 4);
            }
        }
        const uint32_t sb = sm + buf * STAGE_B;
        #pragma unroll
        for (int ks = 0; ks < 4; ++ks) {
            uint32_t ah[2][4], al[2][4], bh[4][2], bl[4][2];
            #pragma unroll
            for (int mt = 0; mt < 2; ++mt) {
                uint32_t ad = sb + a_off + (uint32_t)(mt * 16 * TSTR + ks * 32);
                ldmx4(ah[mt][0], ah[mt][1], ah[mt][2], ah[mt][3], ad + OFF_AHI);
                ldmx4(al[mt][0], al[mt][1], al[mt][2], al[mt][3], ad + OFF_ALO);
            }
            #pragma unroll
            for (int np = 0; np < 2; ++np) {
                uint32_t ad = sb + b_off + (uint32_t)(np * 16 * TSTR + ks * 32);
                ldmx4(bh[np * 2][0], bh[np * 2][1], bh[np * 2 + 1][0], bh[np * 2 + 1][1], ad);
                ldmx4(bl[np * 2][0], bl[np * 2][1], bl[np * 2 + 1][0], bl[np * 2 + 1][1], ad + TILE_B);
            }
            #pragma unroll
            for (int mt = 0; mt < 2; ++mt)
                #pragma unroll
                for (int nt = 0; nt < 4; ++nt) {
                    mma16816(c[mt][nt], ah[mt], bh[nt]);
                    mma16816(c[mt][nt], ah[mt], bl[nt]);
                    mma16816(c[mt][nt], al[mt], bh[nt]);
                }
        }
        if (ch + 1 < nch)
            store_stage(smem + (buf ^ 1) * STAGE_B, t, pa, pb);
        __syncthreads();
        buf ^= 1;
    }
}

#define ACC_INIT4(c) \
    _Pragma("unroll") for (int mt = 0; mt < 2; ++mt) \
    _Pragma("unroll") for (int nt = 0; nt < 4; ++nt) \
    _Pragma("unroll") for (int i = 0; i < 4; ++i) c[mt][nt][i] = 0.f

// ---------------------------------------------------------------------------
// Generic NT GEMM (out-projection; fp32 out + bias) — unchanged R11
// ---------------------------------------------------------------------------
__global__ __launch_bounds__(512) void gemm_nt_mma(
    const float* __restrict__ A, int lda,
    const float* __restrict__ B, int ldb,
    float* __restrict__ C, int ldc, int K,
    const float* __restrict__ bias)
{
    const int m0 = blockIdx.y * 128, n0 = blockIdx.x * 128;
    float c[2][4][4];
    ACC_INIT4(c);

    mma_mainloop(A + (size_t)m0 * lda, lda, B + (size_t)n0 * ldb, ldb, K, c);

    const int lane = threadIdx.x & 31, warp = threadIdx.x >> 5;
    const int rb = m0 + (warp >> 2) * 32 + (lane >> 2);
    const int cb = n0 + (warp & 3) * 32 + (lane & 3) * 2;
    #pragma unroll
    for (int mt = 0; mt < 2; ++mt)
        #pragma unroll
        for (int nt = 0; nt < 4; ++nt) {
            int row = rb + mt * 16, col = cb + nt * 8;
            float b0 = bias ? bias[col] : 0.f, b1 = bias ? bias[col + 1] : 0.f;
            *(float2*)(C + (size_t)row * ldc + col)       = make_float2(c[mt][nt][0] + b0, c[mt][nt][1] + b1);
            *(float2*)(C + (size_t)(row + 8) * ldc + col) = make_float2(c[mt][nt][2] + b0, c[mt][nt][3] + b1);
        }
}

// ---------------------------------------------------------------------------
// QKV GEMM with FUSED epilogue: rope+split for Q/K tiles, transpose+split
// for V tiles. Tiles (blockIdx.x): 0..15 Q heads, 16..19 K heads, 20..23 V.
// ---------------------------------------------------------------------------
__global__ __launch_bounds__(512) void gemm_qkv_fused(
    const float* __restrict__ A, int lda,
    const float* __restrict__ B, int ldb, int K,
    const float* __restrict__ cosb, const float* __restrict__ sinb)
{
    const int m0 = blockIdx.y * 128, n0 = blockIdx.x * 128;
    float c[2][4][4];
    ACC_INIT4(c);

    mma_mainloop(A + (size_t)m0 * lda, lda, B + (size_t)n0 * ldb, ldb, K, c);

    // stage accumulators to smem fp32 [128][ESTR]
    extern __shared__ __align__(16) char smem[];
    float* st = (float*)smem;
    const int t = threadIdx.x, lane = t & 31, warp = t >> 5;
    const int srow = (warp >> 2) * 32 + (lane >> 2);
    const int scol = (warp & 3) * 32 + (lane & 3) * 2;
    #pragma unroll
    for (int mt = 0; mt < 2; ++mt)
        #pragma unroll
        for (int nt = 0; nt < 4; ++nt) {
            int r = srow + mt * 16, cc = scol + nt * 8;
            *(float2*)&st[r * ESTR + cc]       = make_float2(c[mt][nt][0], c[mt][nt][1]);
            *(float2*)&st[(r + 8) * ESTR + cc] = make_float2(c[mt][nt][2], c[mt][nt][3]);
        }
    __syncthreads();

    const int tile = blockIdx.x;
    if (tile < 20) {
        // RoPE tiles (Q head = tile, or K head = tile-16)
        #pragma unroll
        for (int i = 0; i < 4; ++i) {
            int idx = t + i * 512;
            int row = idx >> 4;           // 0..127
            int dq  = (idx & 15) * 4;     // 0..60 step 4
            int gr  = m0 + row;           // = b*NN + n
            int n   = gr & (NN - 1);
            float4 v1 = *(float4*)&st[row * ESTR + dq];
            float4 v2 = *(float4*)&st[row * ESTR + dq + 64];
            float4 cv = *(const float4*)(cosb + n * 64 + dq);
            float4 sv = *(const float4*)(sinb + n * 64 + dq);
            float4 r1 = make_float4(v1.x * cv.x + v2.x * sv.x, v1.y * cv.y + v2.y * sv.y,
                                    v1.z * cv.z + v2.z * sv.z, v1.w * cv.w + v2.w * sv.w);
            float4 r2 = make_float4(v2.x * cv.x - v1.x * sv.x, v2.y * cv.y - v1.y * sv.y,
                                    v2.z * cv.z - v1.z * sv.z, v2.w * cv.w - v1.w * sv.w);
            uint2 hi1, lo1, hi2, lo2;
            split4(r1, hi1, lo1);
            split4(r2, hi2, lo2);
            if (tile < 16) {
                size_t o = ((size_t)gr * HH + tile) * HD + dq;
                *(uint2*)(g_Qh + o)      = hi1;
                *(uint2*)(g_Ql + o)      = lo1;
                *(uint2*)(g_Qh + o + 64) = hi2;
                *(uint2*)(g_Ql + o + 64) = lo2;
            } else {
                size_t o = ((size_t)gr * HKV + (tile - 16)) * HD + dq;
                *(uint2*)(g_Kh + o)      = hi1;
                *(uint2*)(g_Kl + o)      = lo1;
                *(uint2*)(g_Kh + o + 64) = hi2;
                *(uint2*)(g_Kl + o + 64) = lo2;
            }
        }
    } else {
        // V tiles: transpose + split. rows = n (all same b), cols = hd.
        const int hkv = tile - 20;
        const int b   = m0 / NN;
        const int nb  = m0 & (NN - 1);    // n offset of this tile
        size_t base = ((size_t)(b * HKV + hkv)) * HD * NN;
        #pragma unroll
        for (int i = 0; i < 8; ++i) {
            int idx = t + i * 512;
            int d  = idx >> 5;            // 0..127
            int nq = (idx & 31) * 4;      // 0..124 step 4
            float4 vv = make_float4(st[(nq + 0) * ESTR + d], st[(nq + 1) * ESTR + d],
                                    st[(nq + 2) * ESTR + d], st[(nq + 3) * ESTR + d]);
            uint2 hi, lo;
            split4(vv, hi, lo);
            size_t o = base + (size_t)d * NN + nb + nq;
            *(uint2*)(g_Vth + o) = hi;
            *(uint2*)(g_Vtl + o) = lo;
        }
    }
}

// ---------------------------------------------------------------------------
// Fused flash attention — R11 (256 threads, pre-split bf16 hi/lo operands)
// ---------------------------------------------------------------------------
__global__ __launch_bounds__(256) void flash_attn(const float* __restrict__ mask)
{
    extern __shared__ __align__(16) char smem[];
    const int z = blockIdx.z, b = z / HH, h = z % HH, hkv = h % HKV;
    const int m0 = blockIdx.y * 128;
    const int t = threadIdx.x, lane = t & 31, w = t >> 5;
    const uint32_t sm = smem_u32(smem);

    {
        const __nv_bfloat16* Qh = g_Qh + ((size_t)(b * NN + m0) * HH + h) * HD;
        const __nv_bfloat16* Ql = g_Ql + ((size_t)(b * NN + m0) * HH + h) * HD;
        #pragma unroll
        for (int i = 0; i < 8; ++i) {
            int idx = t + i * 256, row = idx >> 4, c16 = idx & 15;
            uint32_t off = (uint32_t)(row * KSTR + c16 * 16);
            size_t g = (size_t)row * (HH * HD) + c16 * 8;
            *(uint4*)(smem + F_QHI + off) = *(const uint4*)(Qh + g);
            *(uint4*)(smem + F_QLO + off) = *(const uint4*)(Ql + g);
        }
    }

    float co[16][4];
    #pragma unroll
    for (int nt = 0; nt < 16; ++nt)
        #pragma unroll
        for (int i = 0; i < 4; ++i) co[nt][i] = 0.f;
    float m0r = -INFINITY, m1r = -INFINITY;
    float l0r = 0.f, l1r = 0.f;

    const uint32_t qa_off = (uint32_t)((w * 16 + (lane & 15)) * KSTR + (lane >> 4) * 16);
    const uint32_t kb_base = (uint32_t)(((lane >> 4) * 8 + (lane & 7)) * KSTR + ((lane >> 3) & 1) * 16);
    const uint32_t pa_off = (uint32_t)((w * 16 + (lane & 15)) * VSTR + (lane >> 4) * 16);
    const uint32_t vb_base = (uint32_t)(((lane >> 4) * 8 + (lane & 7)) * VSTR + ((lane >> 3) & 1) * 16);

    __syncthreads();

    for (int ch = 0; ch < NN / 64; ++ch) {
        const int n0 = ch * 64;
        {
            const __nv_bfloat16* Kh = g_Kh + ((size_t)(b * NN + n0) * HKV + hkv) * HD;
            const __nv_bfloat16* Kl = g_Kl + ((size_t)(b * NN + n0) * HKV + hkv) * HD;
            #pragma unroll
            for (int i = 0; i < 4; ++i) {
                int idx = t + i * 256, row = idx >> 4, c16 = idx & 15;
                uint32_t off = (uint32_t)(row * KSTR + c16 * 16);
                size_t g = (size_t)row * (HKV * HD) + c16 * 8;
                *(uint4*)(smem + F_KHI + off) = *(const uint4*)(Kh + g);
                *(uint4*)(smem + F_KLO + off) = *(const uint4*)(Kl + g);
            }
        }
        {
            const __nv_bfloat16* Vh = g_Vth + (size_t)(b * HKV + hkv) * HD * NN + n0;
            const __nv_bfloat16* Vl = g_Vtl + (size_t)(b * HKV + hkv) * HD * NN + n0;
            #pragma unroll
            for (int i = 0; i < 4; ++i) {
                int idx = t + i * 256, row = idx >> 3, c16 = idx & 7;
                uint32_t off = (uint32_t)(row * VSTR + c16 * 16);
                size_t g = (size_t)row * NN + c16 * 8;
                *(uint4*)(smem + F_VHI + off) = *(const uint4*)(Vh + g);
                *(uint4*)(smem + F_VLO + off) = *(const uint4*)(Vl + g);
            }
        }
        __syncthreads();

        float cs[8][4];
        #pragma unroll
        for (int nt = 0; nt < 8; ++nt)
            #pragma unroll
            for (int i = 0; i < 4; ++i) cs[nt][i] = 0.f;

        #pragma unroll
        for (int ks = 0; ks < 8; ++ks) {
            uint32_t ah[4], al[4];
            uint32_t ad = sm + qa_off + (uint32_t)(ks * 32);
            ldmx4(ah[0], ah[1], ah[2], ah[3], ad + F_QHI);
            ldmx4(al[0], al[1], al[2], al[3], ad + F_QLO);
            #pragma unroll
            for (int np = 0; np < 4; ++np) {
                uint32_t bd = sm + kb_base + (uint32_t)(np * 16 * KSTR + ks * 32);
                uint32_t bh[2][2], bl[2][2];
                ldmx4(bh[0][0], bh[0][1], bh[1][0], bh[1][1], bd + F_KHI);
                ldmx4(bl[0][0], bl[0][1], bl[1][0], bl[1][1], bd + F_KLO);
                #pragma unroll
                for (int q = 0; q < 2; ++q) {
                    mma16816(cs[np * 2 + q], ah, bh[q]);
                    mma16816(cs[np * 2 + q], ah, bl[q]);
                    mma16816(cs[np * 2 + q], al, bh[q]);
                }
            }
        }

        #pragma unroll
        for (int nt = 0; nt < 8; ++nt) {
            int col = n0 + nt * 8 + (lane & 3) * 2;
            float mb0 = (1.0f - mask[b * NN + col]) * -1e9f;
            float mb1 = (1.0f - mask[b * NN + col + 1]) * -1e9f;
            cs[nt][0] = cs[nt][0] * SCALE + mb0;
            cs[nt][1] = cs[nt][1] * SCALE + mb1;
            cs[nt][2] = cs[nt][2] * SCALE + mb0;
            cs[nt][3] = cs[nt][3] * SCALE + mb1;
        }

        float cm0 = -INFINITY, cm1 = -INFINITY;
        #pragma unroll
        for (int nt = 0; nt < 8; ++nt) {
            cm0 = fmaxf(cm0, fmaxf(cs[nt][0], cs[nt][1]));
            cm1 = fmaxf(cm1, fmaxf(cs[nt][2], cs[nt][3]));
        }
        cm0 = fmaxf(cm0, __shfl_xor_sync(0xFFFFFFFF, cm0, 1));
        cm0 = fmaxf(cm0, __shfl_xor_sync(0xFFFFFFFF, cm0, 2));
        cm1 = fmaxf(cm1, __shfl_xor_sync(0xFFFFFFFF, cm1, 1));
        cm1 = fmaxf(cm1, __shfl_xor_sync(0xFFFFFFFF, cm1, 2));

        float mn0 = fmaxf(m0r, cm0), mn1 = fmaxf(m1r, cm1);
        float f0 = __expf(m0r - mn0), f1 = __expf(m1r - mn1);
        m0r = mn0; m1r = mn1;

        float rs0 = 0.f, rs1 = 0.f;
        #pragma unroll
        for (int nt = 0; nt < 8; ++nt) {
            cs[nt][0] = __expf(cs[nt][0] - mn0);
            cs[nt][1] = __expf(cs[nt][1] - mn0);
            cs[nt][2] = __expf(cs[nt][2] - mn1);
            cs[nt][3] = __expf(cs[nt][3] - mn1);
            rs0 += cs[nt][0] + cs[nt][1];
            rs1 += cs[nt][2] + cs[nt][3];
        }
        rs0 += __shfl_xor_sync(0xFFFFFFFF, rs0, 1);
        rs0 += __shfl_xor_sync(0xFFFFFFFF, rs0, 2);
        rs1 += __shfl_xor_sync(0xFFFFFFFF, rs1, 1);
        rs1 += __shfl_xor_sync(0xFFFFFFFF, rs1, 2);
        l0r = l0r * f0 + rs0;
        l1r = l1r * f1 + rs1;

        #pragma unroll
        for (int nt = 0; nt < 16; ++nt) {
            co[nt][0] *= f0; co[nt][1] *= f0;
            co[nt][2] *= f1; co[nt][3] *= f1;
        }

        {
            int r0 = lane >> 2;
            uint32_t base0 = (uint32_t)((w * 16 + r0) * VSTR + (lane & 3) * 4);
            #pragma unroll
            for (int nt = 0; nt < 8; ++nt) {
                uint32_t hi, lo;
                split2(cs[nt][0], cs[nt][1], hi, lo);
                uint32_t o0 = base0 + nt * 16;
                *(uint32_t*)(smem + F_PHI + o0) = hi;
                *(uint32_t*)(smem + F_PLO + o0) = lo;
                split2(cs[nt][2], cs[nt][3], hi, lo);
                uint32_t o1 = o0 + 8 * VSTR;
                *(uint32_t*)(smem + F_PHI + o1) = hi;
                *(uint32_t*)(smem + F_PLO + o1) = lo;
            }
        }
        __syncthreads();

        #pragma unroll
        for (int ks = 0; ks < 4; ++ks) {
            uint32_t ah[4], al[4];
            uint32_t ad = sm + pa_off + (uint32_t)(ks * 32);
            ldmx4(ah[0], ah[1], ah[2], ah[3], ad + F_PHI);
            ldmx4(al[0], al[1], al[2], al[3], ad + F_PLO);
            #pragma unroll
            for (int np = 0; np < 8; ++np) {
                uint32_t bd = sm + vb_base + (uint32_t)(np * 16 * VSTR + ks * 32);
                uint32_t bh[2][2], bl[2][2];
                ldmx4(bh[0][0], bh[0][1], bh[1][0], bh[1][1], bd + F_VHI);
                ldmx4(bl[0][0], bl[0][1], bl[1][0], bl[1][1], bd + F_VLO);
                #pragma unroll
                for (int q = 0; q < 2; ++q) {
                    mma16816(co[np * 2 + q], ah, bh[q]);
                    mma16816(co[np * 2 + q], ah, bl[q]);
                    mma16816(co[np * 2 + q], al, bh[q]);
                }
            }
        }
        __syncthreads();
    }

    float inv0 = 1.0f / l0r, inv1 = 1.0f / l1r;
    int r0 = lane >> 2;
    #pragma unroll
    for (int nt = 0; nt < 16; ++nt) {
        int row = m0 + w * 16 + r0;
        int col = nt * 8 + (lane & 3) * 2;
        float* p0 = g_ctx + (size_t)(b * NN + row) * (HH * HD) + h * HD + col;
        float* p1 = g_ctx + (size_t)(b * NN + row + 8) * (HH * HD) + h * HD + col;
        *(float2*)p0 = make_float2(co[nt][0] * inv0, co[nt][1] * inv0);
        *(float2*)p1 = make_float2(co[nt][2] * inv1, co[nt][3] * inv1);
    }
}

// ---------------------------------------------------------------------------
// Weight transposes (fp32 — unchanged)
// ---------------------------------------------------------------------------
__global__ void transpose_f32(const float* __restrict__ src, float* __restrict__ dst,
                              int R, int C)
{
    __shared__ float tile[32][33];
    int c0 = blockIdx.x * 32, r0 = blockIdx.y * 32;
    int tx = threadIdx.x, ty = threadIdx.y;
    #pragma unroll
    for (int i = ty; i < 32; i += 8)
        tile[i][tx] = src[(size_t)(r0 + i) * C + c0 + tx];
    __syncthreads();
    #pragma unroll
    for (int i = ty; i < 32; i += 8)
        dst[(size_t)(c0 + i) * R + r0 + tx] = tile[tx][i];
}

// ---------------------------------------------------------------------------
// Launch
// ---------------------------------------------------------------------------
extern "C" void kernel_launch(void* const* d_in, const int* in_sizes, int n_in,
                              void* d_out, int out_size)
{
    (void)in_sizes; (void)n_in; (void)out_size;

    const float* x    = (const float*)d_in[0];
    const float* cosb = (const float*)d_in[1];
    const float* sinb = (const float*)d_in[2];
    const float* mask = (const float*)d_in[3];
    const float* Wq   = (const float*)d_in[4];
    const float* Wkv  = (const float*)d_in[5];
    const float* Wo   = (const float*)d_in[6];
    const float* bo   = (const float*)d_in[7];
    float* out = (float*)d_out;

    float *pWT, *pWoT, *pCtx;
    cudaGetSymbolAddress((void**)&pWT,  g_WT);
    cudaGetSymbolAddress((void**)&pWoT, g_WoT);
    cudaGetSymbolAddress((void**)&pCtx, g_ctx);

    cudaFuncSetAttribute(gemm_nt_mma,    cudaFuncAttributeMaxDynamicSharedMemorySize, SMEM_SZ);
    cudaFuncSetAttribute(gemm_qkv_fused, cudaFuncAttributeMaxDynamicSharedMemorySize, SMEM_SZ);
    cudaFuncSetAttribute(flash_attn,     cudaFuncAttributeMaxDynamicSharedMemorySize, F_SZ);

    const int M = BB * NN;   // 4096
    dim3 tb(32, 8);

    // Weight transposes
    transpose_f32<<<dim3(DD / 32, DD / 32), tb>>>(Wq, pWT, DD, DD);
    transpose_f32<<<dim3((2 * HKV * HD) / 32, DD / 32), tb>>>(Wkv, pWT + (size_t)KOFF * DD, DD, 2 * HKV * HD);
    transpose_f32<<<dim3(DD / 32, DD / 32), tb>>>(Wo, pWoT, DD, DD);

    // QKV = x @ [Wq|Wkv] with fused rope/split/V-transpose epilogue
    gemm_qkv_fused<<<dim3(QKVW / 128, M / 128), 512, SMEM_SZ>>>(
        x, DD, pWT, DD, DD, cosb, sinb);

    // fused attention
    flash_attn<<<dim3(1, NN / 128, BB * HH), 256, F_SZ>>>(mask);

    // out = ctx @ Wo + bo
    gemm_nt_mma<<<dim3(DD / 128, M / 128), 512, SMEM_SZ>>>(pCtx, HH * HD, pWoT, DD, out, DD, DD, bo);
}

// round 17
// speedup vs baseline: 1.0197x; 1.0125x over previous
#include <cuda_runtime.h>
#include <cuda_bf16.h>
#include <math.h>
#include <cstdint>

// ---------------------------------------------------------------------------
// Problem constants
// ---------------------------------------------------------------------------
#define BB   2
#define NN   2048
#define DD   2048
#define HH   16
#define HKV  4
#define HD   128
#define QKVW (HH * HD + 2 * HKV * HD)     // 3072
#define KOFF (HH * HD)                    // 2048
#define SCALE 0.08838834764831845f

#define BK 64
#define TSTR 144
#define TILE_B (128 * TSTR)
#define STAGE_B (4 * TILE_B)
#define SMEM_SZ (2 * STAGE_B)  // 147456
#define OFF_AHI 0
#define OFF_ALO (TILE_B)
#define OFF_BHI (2 * TILE_B)
#define OFF_BLO (3 * TILE_B)

// flash-attention smem layout (R11)
#define KSTR 272
#define VSTR 144
#define F_QHI 0
#define F_QLO (F_QHI + 128 * KSTR)
#define F_KHI (F_QLO + 128 * KSTR)
#define F_KLO (F_KHI + 64 * KSTR)
#define F_VHI (F_KLO + 64 * KSTR)
#define F_VLO (F_VHI + 128 * VSTR)
#define F_PHI (F_VLO + 128 * VSTR)
#define F_PLO (F_PHI + 128 * VSTR)
#define F_SZ  (F_PLO + 128 * VSTR)    // 178176

// ---------------------------------------------------------------------------
// Device scratch
// ---------------------------------------------------------------------------
__device__ float g_WT [(size_t)QKVW * DD];                 // 24 MB
__device__ float g_WoT[(size_t)DD * DD];                   // 16 MB
__device__ float g_ctx[(size_t)BB * NN * HH * HD];         // 32 MB
__device__ float g_V  [(size_t)BB * NN * HKV * HD];        // 8 MB (fp32 V staging)

__device__ __align__(128) __nv_bfloat16 g_Qh [(size_t)BB * NN * HH * HD];
__device__ __align__(128) __nv_bfloat16 g_Ql [(size_t)BB * NN * HH * HD];
__device__ __align__(128) __nv_bfloat16 g_Kh [(size_t)BB * NN * HKV * HD];
__device__ __align__(128) __nv_bfloat16 g_Kl [(size_t)BB * NN * HKV * HD];
__device__ __align__(128) __nv_bfloat16 g_Vth[(size_t)BB * HKV * HD * NN];
__device__ __align__(128) __nv_bfloat16 g_Vtl[(size_t)BB * HKV * HD * NN];

// ---------------------------------------------------------------------------
// PTX helpers
// ---------------------------------------------------------------------------
__device__ __forceinline__ uint32_t smem_u32(const void* p) {
    uint32_t a;
    asm("{ .reg .u64 t; cvta.to.shared.u64 t, %1; cvt.u32.u64 %0, t; }" : "=r"(a) : "l"(p));
    return a;
}
__device__ __forceinline__ void ldmx4(uint32_t& r0, uint32_t& r1, uint32_t& r2, uint32_t& r3, uint32_t addr) {
    asm volatile("ldmatrix.sync.aligned.m8n8.x4.shared.b16 {%0,%1,%2,%3}, [%4];"
                 : "=r"(r0), "=r"(r1), "=r"(r2), "=r"(r3) : "r"(addr));
}
__device__ __forceinline__ void mma16816(float* c, const uint32_t* a, const uint32_t* b) {
    asm volatile(
        "mma.sync.aligned.m16n8k16.row.col.f32.bf16.bf16.f32 "
        "{%0,%1,%2,%3}, {%4,%5,%6,%7}, {%8,%9}, {%0,%1,%2,%3};"
        : "+f"(c[0]), "+f"(c[1]), "+f"(c[2]), "+f"(c[3])
        : "r"(a[0]), "r"(a[1]), "r"(a[2]), "r"(a[3]), "r"(b[0]), "r"(b[1]));
}

__device__ __forceinline__ void split4(float4 v, uint2& hi, uint2& lo) {
    __nv_bfloat16 hx = __float2bfloat16(v.x), hy = __float2bfloat16(v.y),
                  hz = __float2bfloat16(v.z), hw = __float2bfloat16(v.w);
    __nv_bfloat162 h01 = __halves2bfloat162(hx, hy), h23 = __halves2bfloat162(hz, hw);
    __nv_bfloat16 lx = __float2bfloat16(v.x - __bfloat162float(hx));
    __nv_bfloat16 ly = __float2bfloat16(v.y - __bfloat162float(hy));
    __nv_bfloat16 lz = __float2bfloat16(v.z - __bfloat162float(hz));
    __nv_bfloat16 lw = __float2bfloat16(v.w - __bfloat162float(hw));
    __nv_bfloat162 l01 = __halves2bfloat162(lx, ly), l23 = __halves2bfloat162(lz, lw);
    hi = make_uint2(*(uint32_t*)&h01, *(uint32_t*)&h23);
    lo = make_uint2(*(uint32_t*)&l01, *(uint32_t*)&l23);
}
__device__ __forceinline__ void split2(float a, float b, uint32_t& hi, uint32_t& lo) {
    __nv_bfloat16 ha = __float2bfloat16(a), hb = __float2bfloat16(b);
    __nv_bfloat16 la = __float2bfloat16(a - __bfloat162float(ha));
    __nv_bfloat16 lb = __float2bfloat16(b - __bfloat162float(hb));
    __nv_bfloat162 hp = __halves2bfloat162(ha, hb), lp = __halves2bfloat162(la, lb);
    hi = *(uint32_t*)&hp; lo = *(uint32_t*)&lp;
}
__device__ __forceinline__ void split1(float v, __nv_bfloat16& h, __nv_bfloat16& l) {
    h = __float2bfloat16(v);
    l = __float2bfloat16(v - __bfloat162float(h));
}

// gemm stage store — BK=64, 512 threads
__device__ __forceinline__ void store_stage(char* sb, int t, const float4* pa, const float4* pb) {
    #pragma unroll
    for (int i = 0; i < 4; ++i) {
        int idx = t + i * 512, row = idx >> 4, c4 = idx & 15;
        uint32_t off = (uint32_t)(row * TSTR + c4 * 8);
        uint2 hi, lo;
        split4(pa[i], hi, lo);
        *(uint2*)(sb + OFF_AHI + off) = hi;
        *(uint2*)(sb + OFF_ALO + off) = lo;
        split4(pb[i], hi, lo);
        *(uint2*)(sb + OFF_BHI + off) = hi;
        *(uint2*)(sb + OFF_BLO + off) = lo;
    }
}

// ---------------------------------------------------------------------------
// GEMM mainloop — R11 structure; PAIRED selects B-fragment row mapping:
//   PAIRED=0: warp cols = wn*32 + np*16 + q*8  (normal)
//   PAIRED=1: warp cols = wn*16 + np*64 + q*8  (RoPE pairs d,d+64 in-regs)
// ---------------------------------------------------------------------------
template<int PAIRED>
__device__ __forceinline__ void mma_mainloop(
    const float* __restrict__ A, int lda,
    const float* __restrict__ B, int ldb, int K,
    float c[2][4][4])
{
    extern __shared__ __align__(16) char smem[];
    const int t    = threadIdx.x;
    const int lane = t & 31;
    const int warp = t >> 5;
    const int wm   = warp >> 2;
    const int wn   = warp & 3;
    const uint32_t sm = smem_u32(smem);

    const int bbase = PAIRED ? (wn * 16) : (wn * 32);
    const int bstep = PAIRED ? 64 : 16;

    const uint32_t a_off = (uint32_t)((wm * 32 + (lane & 15)) * TSTR + (lane >> 4) * 16);
    const uint32_t b_off = (uint32_t)(OFF_BHI + (bbase + (lane >> 4) * 8 + (lane & 7)) * TSTR + ((lane >> 3) & 1) * 16);

    float4 pa[4], pb[4];
    const int nch = K / BK;

    #pragma unroll
    for (int i = 0; i < 4; ++i) {
        int idx = t + i * 512, row = idx >> 4, c4 = idx & 15;
        pa[i] = *(const float4*)(A + (size_t)row * lda + c4 * 4);
        pb[i] = *(const float4*)(B + (size_t)row * ldb + c4 * 4);
    }
    store_stage(smem, t, pa, pb);
    __syncthreads();

    uint32_t buf = 0;
    for (int ch = 0; ch < nch; ++ch) {
        if (ch + 1 < nch) {
            const int k0 = (ch + 1) * BK;
            #pragma unroll
            for (int i = 0; i < 4; ++i) {
                int idx = t + i * 512, row = idx >> 4, c4 = idx & 15;
                pa[i] = *(const float4*)(A + (size_t)row * lda + k0 + c4 * 4);
                pb[i] = *(const float4*)(B + (size_t)row * ldb + k0 + c4 * 4);
            }
        }
        const uint32_t sb = sm + buf * STAGE_B;
        #pragma unroll
        for (int ks = 0; ks < 4; ++ks) {
            uint32_t ah[2][4], al[2][4], bh[4][2], bl[4][2];
            #pragma unroll
            for (int mt = 0; mt < 2; ++mt) {
                uint32_t ad = sb + a_off + (uint32_t)(mt * 16 * TSTR + ks * 32);
                ldmx4(ah[mt][0], ah[mt][1], ah[mt][2], ah[mt][3], ad + OFF_AHI);
                ldmx4(al[mt][0], al[mt][1], al[mt][2], al[mt][3], ad + OFF_ALO);
            }
            #pragma unroll
            for (int np = 0; np < 2; ++np) {
                uint32_t ad = sb + b_off + (uint32_t)(np * bstep * TSTR + ks * 32);
                ldmx4(bh[np * 2][0], bh[np * 2][1], bh[np * 2 + 1][0], bh[np * 2 + 1][1], ad);
                ldmx4(bl[np * 2][0], bl[np * 2][1], bl[np * 2 + 1][0], bl[np * 2 + 1][1], ad + TILE_B);
            }
            #pragma unroll
            for (int mt = 0; mt < 2; ++mt)
                #pragma unroll
                for (int nt = 0; nt < 4; ++nt) {
                    mma16816(c[mt][nt], ah[mt], bh[nt]);
                    mma16816(c[mt][nt], ah[mt], bl[nt]);
                    mma16816(c[mt][nt], al[mt], bh[nt]);
                }
        }
        if (ch + 1 < nch)
            store_stage(smem + (buf ^ 1) * STAGE_B, t, pa, pb);
        __syncthreads();
        buf ^= 1;
    }
}

#define ACC_INIT4(c) \
    _Pragma("unroll") for (int mt = 0; mt < 2; ++mt) \
    _Pragma("unroll") for (int nt = 0; nt < 4; ++nt) \
    _Pragma("unroll") for (int i = 0; i < 4; ++i) c[mt][nt][i] = 0.f

// ---------------------------------------------------------------------------
// Generic NT GEMM (out-projection) — unchanged R11 (normal mapping)
// ---------------------------------------------------------------------------
__global__ __launch_bounds__(512) void gemm_nt_mma(
    const float* __restrict__ A, int lda,
    const float* __restrict__ B, int ldb,
    float* __restrict__ C, int ldc, int K,
    const float* __restrict__ bias)
{
    const int m0 = blockIdx.y * 128, n0 = blockIdx.x * 128;
    float c[2][4][4];
    ACC_INIT4(c);

    mma_mainloop<0>(A + (size_t)m0 * lda, lda, B + (size_t)n0 * ldb, ldb, K, c);

    const int lane = threadIdx.x & 31, warp = threadIdx.x >> 5;
    const int rb = m0 + (warp >> 2) * 32 + (lane >> 2);
    const int cb = n0 + (warp & 3) * 32 + (lane & 3) * 2;
    #pragma unroll
    for (int mt = 0; mt < 2; ++mt)
        #pragma unroll
        for (int nt = 0; nt < 4; ++nt) {
            int row = rb + mt * 16, col = cb + nt * 8;
            float b0 = bias ? bias[col] : 0.f, b1 = bias ? bias[col + 1] : 0.f;
            *(float2*)(C + (size_t)row * ldc + col)       = make_float2(c[mt][nt][0] + b0, c[mt][nt][1] + b1);
            *(float2*)(C + (size_t)(row + 8) * ldc + col) = make_float2(c[mt][nt][2] + b0, c[mt][nt][3] + b1);
        }
}

// ---------------------------------------------------------------------------
// QKV GEMM, PAIRED mapping, register-resident RoPE epilogue.
// Tiles (blockIdx.x): 0..15 Q heads, 16..19 K heads, 20..23 V heads.
// Thread accumulator cols: d = wn*16 + (nt&1)*8 + (lane&3)*2, partner d+64
// in c[mt][nt+2]. Rows: rb + mt*16 (+8 for elems [2],[3]).
// ---------------------------------------------------------------------------
__global__ __launch_bounds__(512) void gemm_qkv_fused(
    const float* __restrict__ A, int lda,
    const float* __restrict__ B, int ldb, int K,
    const float* __restrict__ cosb, const float* __restrict__ sinb)
{
    const int m0 = blockIdx.y * 128;
    const int tile = blockIdx.x;
    float c[2][4][4];
    ACC_INIT4(c);

    mma_mainloop<1>(A + (size_t)m0 * lda, lda, B + (size_t)(tile * 128) * ldb, ldb, K, c);

    const int t = threadIdx.x, lane = t & 31, warp = t >> 5;
    const int rloc = (warp >> 2) * 32 + (lane >> 2);
    const int dbase = (warp & 3) * 16 + (lane & 3) * 2;

    #pragma unroll
    for (int mt = 0; mt < 2; ++mt) {
        const int gr = m0 + rloc + mt * 16;     // b*NN + n (row 0 of this pair)
        const int na = gr & (NN - 1);
        const int nb = na + 8;                  // row +8, same tile so same b
        #pragma unroll
        for (int nt = 0; nt < 2; ++nt) {
            const int d = dbase + nt * 8;
            const float* v1 = c[mt][nt];        // cols d, d+1 (rows gr, gr+8)
            const float* v2 = c[mt][nt + 2];    // cols d+64, d+65

            if (tile < 20) {
                float2 ca = *(const float2*)(cosb + na * 64 + d);
                float2 sa = *(const float2*)(sinb + na * 64 + d);
                float2 cbv = *(const float2*)(cosb + nb * 64 + d);
                float2 sb = *(const float2*)(sinb + nb * 64 + d);
                // row gr
                float r1a = v1[0] * ca.x + v2[0] * sa.x;
                float r1b = v1[1] * ca.y + v2[1] * sa.y;
                float r2a = v2[0] * ca.x - v1[0] * sa.x;
                float r2b = v2[1] * ca.y - v1[1] * sa.y;
                // row gr+8
                float r3a = v1[2] * cbv.x + v2[2] * sb.x;
                float r3b = v1[3] * cbv.y + v2[3] * sb.y;
                float r4a = v2[2] * cbv.x - v1[2] * sb.x;
                float r4b = v2[3] * cbv.y - v1[3] * sb.y;

                uint32_t hi, lo;
                if (tile < 16) {
                    size_t o0 = ((size_t)gr * HH + tile) * HD + d;
                    size_t o1 = o0 + (size_t)8 * HH * HD;
                    split2(r1a, r1b, hi, lo); *(uint32_t*)(g_Qh + o0) = hi;      *(uint32_t*)(g_Ql + o0) = lo;
                    split2(r2a, r2b, hi, lo); *(uint32_t*)(g_Qh + o0 + 64) = hi; *(uint32_t*)(g_Ql + o0 + 64) = lo;
                    split2(r3a, r3b, hi, lo); *(uint32_t*)(g_Qh + o1) = hi;      *(uint32_t*)(g_Ql + o1) = lo;
                    split2(r4a, r4b, hi, lo); *(uint32_t*)(g_Qh + o1 + 64) = hi; *(uint32_t*)(g_Ql + o1 + 64) = lo;
                } else {
                    size_t o0 = ((size_t)gr * HKV + (tile - 16)) * HD + d;
                    size_t o1 = o0 + (size_t)8 * HKV * HD;
                    split2(r1a, r1b, hi, lo); *(uint32_t*)(g_Kh + o0) = hi;      *(uint32_t*)(g_Kl + o0) = lo;
                    split2(r2a, r2b, hi, lo); *(uint32_t*)(g_Kh + o0 + 64) = hi; *(uint32_t*)(g_Kl + o0 + 64) = lo;
                    split2(r3a, r3b, hi, lo); *(uint32_t*)(g_Kh + o1) = hi;      *(uint32_t*)(g_Kl + o1) = lo;
                    split2(r4a, r4b, hi, lo); *(uint32_t*)(g_Kh + o1 + 64) = hi; *(uint32_t*)(g_Kl + o1 + 64) = lo;
                }
            } else {
                // V: write fp32 to g_V [gr][hkv][hd]
                size_t o0 = ((size_t)gr * HKV + (tile - 20)) * HD + d;
                size_t o1 = o0 + (size_t)8 * HKV * HD;
                *(float2*)(g_V + o0)      = make_float2(v1[0], v1[1]);
                *(float2*)(g_V + o0 + 64) = make_float2(v2[0], v2[1]);
                *(float2*)(g_V + o1)      = make_float2(v1[2], v1[3]);
                *(float2*)(g_V + o1 + 64) = make_float2(v2[2], v2[3]);
            }
        }
    }
}

// ---------------------------------------------------------------------------
// V transpose + split: g_V [b][n][hkv][hd] -> Vth/Vtl [b][hkv][hd][n]
// ---------------------------------------------------------------------------
__global__ void transpose_v_split()
{
    __shared__ float tile[32][33];
    int z = blockIdx.z, b = z / HKV, hkv = z % HKV;
    int n0 = blockIdx.x * 32, d0 = blockIdx.y * 32;
    int tx = threadIdx.x, ty = threadIdx.y;
    #pragma unroll
    for (int i = ty; i < 32; i += 8)
        tile[i][tx] = g_V[(size_t)(b * NN + n0 + i) * (HKV * HD) + hkv * HD + d0 + tx];
    __syncthreads();
    size_t base = (size_t)(b * HKV + hkv) * HD * NN;
    #pragma unroll
    for (int i = ty; i < 32; i += 8) {
        float v = tile[tx][i];
        __nv_bfloat16 h, l;
        split1(v, h, l);
        size_t off = base + (size_t)(d0 + i) * NN + n0 + tx;
        g_Vth[off] = h; g_Vtl[off] = l;
    }
}

// ---------------------------------------------------------------------------
// Fused flash attention — R11 (256 threads, pre-split bf16 hi/lo operands)
// ---------------------------------------------------------------------------
__global__ __launch_bounds__(256) void flash_attn(const float* __restrict__ mask)
{
    extern __shared__ __align__(16) char smem[];
    const int z = blockIdx.z, b = z / HH, h = z % HH, hkv = h % HKV;
    const int m0 = blockIdx.y * 128;
    const int t = threadIdx.x, lane = t & 31, w = t >> 5;
    const uint32_t sm = smem_u32(smem);

    {
        const __nv_bfloat16* Qh = g_Qh + ((size_t)(b * NN + m0) * HH + h) * HD;
        const __nv_bfloat16* Ql = g_Ql + ((size_t)(b * NN + m0) * HH + h) * HD;
        #pragma unroll
        for (int i = 0; i < 8; ++i) {
            int idx = t + i * 256, row = idx >> 4, c16 = idx & 15;
            uint32_t off = (uint32_t)(row * KSTR + c16 * 16);
            size_t g = (size_t)row * (HH * HD) + c16 * 8;
            *(uint4*)(smem + F_QHI + off) = *(const uint4*)(Qh + g);
            *(uint4*)(smem + F_QLO + off) = *(const uint4*)(Ql + g);
        }
    }

    float co[16][4];
    #pragma unroll
    for (int nt = 0; nt < 16; ++nt)
        #pragma unroll
        for (int i = 0; i < 4; ++i) co[nt][i] = 0.f;
    float m0r = -INFINITY, m1r = -INFINITY;
    float l0r = 0.f, l1r = 0.f;

    const uint32_t qa_off = (uint32_t)((w * 16 + (lane & 15)) * KSTR + (lane >> 4) * 16);
    const uint32_t kb_base = (uint32_t)(((lane >> 4) * 8 + (lane & 7)) * KSTR + ((lane >> 3) & 1) * 16);
    const uint32_t pa_off = (uint32_t)((w * 16 + (lane & 15)) * VSTR + (lane >> 4) * 16);
    const uint32_t vb_base = (uint32_t)(((lane >> 4) * 8 + (lane & 7)) * VSTR + ((lane >> 3) & 1) * 16);

    __syncthreads();

    for (int ch = 0; ch < NN / 64; ++ch) {
        const int n0 = ch * 64;
        {
            const __nv_bfloat16* Kh = g_Kh + ((size_t)(b * NN + n0) * HKV + hkv) * HD;
            const __nv_bfloat16* Kl = g_Kl + ((size_t)(b * NN + n0) * HKV + hkv) * HD;
            #pragma unroll
            for (int i = 0; i < 4; ++i) {
                int idx = t + i * 256, row = idx >> 4, c16 = idx & 15;
                uint32_t off = (uint32_t)(row * KSTR + c16 * 16);
                size_t g = (size_t)row * (HKV * HD) + c16 * 8;
                *(uint4*)(smem + F_KHI + off) = *(const uint4*)(Kh + g);
                *(uint4*)(smem + F_KLO + off) = *(const uint4*)(Kl + g);
            }
        }
        {
            const __nv_bfloat16* Vh = g_Vth + (size_t)(b * HKV + hkv) * HD * NN + n0;
            const __nv_bfloat16* Vl = g_Vtl + (size_t)(b * HKV + hkv) * HD * NN + n0;
            #pragma unroll
            for (int i = 0; i < 4; ++i) {
                int idx = t + i * 256, row = idx >> 3, c16 = idx & 7;
                uint32_t off = (uint32_t)(row * VSTR + c16 * 16);
                size_t g = (size_t)row * NN + c16 * 8;
                *(uint4*)(smem + F_VHI + off) = *(const uint4*)(Vh + g);
                *(uint4*)(smem + F_VLO + off) = *(const uint4*)(Vl + g);
            }
        }
        __syncthreads();

        float cs[8][4];
        #pragma unroll
        for (int nt = 0; nt < 8; ++nt)
            #pragma unroll
            for (int i = 0; i < 4; ++i) cs[nt][i] = 0.f;

        #pragma unroll
        for (int ks = 0; ks < 8; ++ks) {
            uint32_t ah[4], al[4];
            uint32_t ad = sm + qa_off + (uint32_t)(ks * 32);
            ldmx4(ah[0], ah[1], ah[2], ah[3], ad + F_QHI);
            ldmx4(al[0], al[1], al[2], al[3], ad + F_QLO);
            #pragma unroll
            for (int np = 0; np < 4; ++np) {
                uint32_t bd = sm + kb_base + (uint32_t)(np * 16 * KSTR + ks * 32);
                uint32_t bh[2][2], bl[2][2];
                ldmx4(bh[0][0], bh[0][1], bh[1][0], bh[1][1], bd + F_KHI);
                ldmx4(bl[0][0], bl[0][1], bl[1][0], bl[1][1], bd + F_KLO);
                #pragma unroll
                for (int q = 0; q < 2; ++q) {
                    mma16816(cs[np * 2 + q], ah, bh[q]);
                    mma16816(cs[np * 2 + q], ah, bl[q]);
                    mma16816(cs[np * 2 + q], al, bh[q]);
                }
            }
        }

        #pragma unroll
        for (int nt = 0; nt < 8; ++nt) {
            int col = n0 + nt * 8 + (lane & 3) * 2;
            float mb0 = (1.0f - mask[b * NN + col]) * -1e9f;
            float mb1 = (1.0f - mask[b * NN + col + 1]) * -1e9f;
            cs[nt][0] = cs[nt][0] * SCALE + mb0;
            cs[nt][1] = cs[nt][1] * SCALE + mb1;
            cs[nt][2] = cs[nt][2] * SCALE + mb0;
            cs[nt][3] = cs[nt][3] * SCALE + mb1;
        }

        float cm0 = -INFINITY, cm1 = -INFINITY;
        #pragma unroll
        for (int nt = 0; nt < 8; ++nt) {
            cm0 = fmaxf(cm0, fmaxf(cs[nt][0], cs[nt][1]));
            cm1 = fmaxf(cm1, fmaxf(cs[nt][2], cs[nt][3]));
        }
        cm0 = fmaxf(cm0, __shfl_xor_sync(0xFFFFFFFF, cm0, 1));
        cm0 = fmaxf(cm0, __shfl_xor_sync(0xFFFFFFFF, cm0, 2));
        cm1 = fmaxf(cm1, __shfl_xor_sync(0xFFFFFFFF, cm1, 1));
        cm1 = fmaxf(cm1, __shfl_xor_sync(0xFFFFFFFF, cm1, 2));

        float mn0 = fmaxf(m0r, cm0), mn1 = fmaxf(m1r, cm1);
        float f0 = __expf(m0r - mn0), f1 = __expf(m1r - mn1);
        m0r = mn0; m1r = mn1;

        float rs0 = 0.f, rs1 = 0.f;
        #pragma unroll
        for (int nt = 0; nt < 8; ++nt) {
            cs[nt][0] = __expf(cs[nt][0] - mn0);
            cs[nt][1] = __expf(cs[nt][1] - mn0);
            cs[nt][2] = __expf(cs[nt][2] - mn1);
            cs[nt][3] = __expf(cs[nt][3] - mn1);
            rs0 += cs[nt][0] + cs[nt][1];
            rs1 += cs[nt][2] + cs[nt][3];
        }
        rs0 += __shfl_xor_sync(0xFFFFFFFF, rs0, 1);
        rs0 += __shfl_xor_sync(0xFFFFFFFF, rs0, 2);
        rs1 += __shfl_xor_sync(0xFFFFFFFF, rs1, 1);
        rs1 += __shfl_xor_sync(0xFFFFFFFF, rs1, 2);
        l0r = l0r * f0 + rs0;
        l1r = l1r * f1 + rs1;

        #pragma unroll
        for (int nt = 0; nt < 16; ++nt) {
            co[nt][0] *= f0; co[nt][1] *= f0;
            co[nt][2] *= f1; co[nt][3] *= f1;
        }

        {
            int r0 = lane >> 2;
            uint32_t base0 = (uint32_t)((w * 16 + r0) * VSTR + (lane & 3) * 4);
            #pragma unroll
            for (int nt = 0; nt < 8; ++nt) {
                uint32_t hi, lo;
                split2(cs[nt][0], cs[nt][1], hi, lo);
                uint32_t o0 = base0 + nt * 16;
                *(uint32_t*)(smem + F_PHI + o0) = hi;
                *(uint32_t*)(smem + F_PLO + o0) = lo;
                split2(cs[nt][2], cs[nt][3], hi, lo);
                uint32_t o1 = o0 + 8 * VSTR;
                *(uint32_t*)(smem + F_PHI + o1) = hi;
                *(uint32_t*)(smem + F_PLO + o1) = lo;
            }
        }
        __syncthreads();

        #pragma unroll
        for (int ks = 0; ks < 4; ++ks) {
            uint32_t ah[4], al[4];
            uint32_t ad = sm + pa_off + (uint32_t)(ks * 32);
            ldmx4(ah[0], ah[1], ah[2], ah[3], ad + F_PHI);
            ldmx4(al[0], al[1], al[2], al[3], ad + F_PLO);
            #pragma unroll
            for (int np = 0; np < 8; ++np) {
                uint32_t bd = sm + vb_base + (uint32_t)(np * 16 * VSTR + ks * 32);
                uint32_t bh[2][2], bl[2][2];
                ldmx4(bh[0][0], bh[0][1], bh[1][0], bh[1][1], bd + F_VHI);
                ldmx4(bl[0][0], bl[0][1], bl[1][0], bl[1][1], bd + F_VLO);
                #pragma unroll
                for (int q = 0; q < 2; ++q) {
                    mma16816(co[np * 2 + q], ah, bh[q]);
                    mma16816(co[np * 2 + q], ah, bl[q]);
                    mma16816(co[np * 2 + q], al, bh[q]);
                }
            }
        }
        __syncthreads();
    }

    float inv0 = 1.0f / l0r, inv1 = 1.0f / l1r;
    int r0 = lane >> 2;
    #pragma unroll
    for (int nt = 0; nt < 16; ++nt) {
        int row = m0 + w * 16 + r0;
        int col = nt * 8 + (lane & 3) * 2;
        float* p0 = g_ctx + (size_t)(b * NN + row) * (HH * HD) + h * HD + col;
        float* p1 = g_ctx + (size_t)(b * NN + row + 8) * (HH * HD) + h * HD + col;
        *(float2*)p0 = make_float2(co[nt][0] * inv0, co[nt][1] * inv0);
        *(float2*)p1 = make_float2(co[nt][2] * inv1, co[nt][3] * inv1);
    }
}

// ---------------------------------------------------------------------------
// Weight transposes (fp32 — unchanged)
// ---------------------------------------------------------------------------
__global__ void transpose_f32(const float* __restrict__ src, float* __restrict__ dst,
                              int R, int C)
{
    __shared__ float tile[32][33];
    int c0 = blockIdx.x * 32, r0 = blockIdx.y * 32;
    int tx = threadIdx.x, ty = threadIdx.y;
    #pragma unroll
    for (int i = ty; i < 32; i += 8)
        tile[i][tx] = src[(size_t)(r0 + i) * C + c0 + tx];
    __syncthreads();
    #pragma unroll
    for (int i = ty; i < 32; i += 8)
        dst[(size_t)(c0 + i) * R + r0 + tx] = tile[tx][i];
}

// ---------------------------------------------------------------------------
// Launch
// ---------------------------------------------------------------------------
extern "C" void kernel_launch(void* const* d_in, const int* in_sizes, int n_in,
                              void* d_out, int out_size)
{
    (void)in_sizes; (void)n_in; (void)out_size;

    const float* x    = (const float*)d_in[0];
    const float* cosb = (const float*)d_in[1];
    const float* sinb = (const float*)d_in[2];
    const float* mask = (const float*)d_in[3];
    const float* Wq   = (const float*)d_in[4];
    const float* Wkv  = (const float*)d_in[5];
    const float* Wo   = (const float*)d_in[6];
    const float* bo   = (const float*)d_in[7];
    float* out = (float*)d_out;

    float *pWT, *pWoT, *pCtx;
    cudaGetSymbolAddress((void**)&pWT,  g_WT);
    cudaGetSymbolAddress((void**)&pWoT, g_WoT);
    cudaGetSymbolAddress((void**)&pCtx, g_ctx);

    cudaFuncSetAttribute(gemm_nt_mma,    cudaFuncAttributeMaxDynamicSharedMemorySize, SMEM_SZ);
    cudaFuncSetAttribute(gemm_qkv_fused, cudaFuncAttributeMaxDynamicSharedMemorySize, SMEM_SZ);
    cudaFuncSetAttribute(flash_attn,     cudaFuncAttributeMaxDynamicSharedMemorySize, F_SZ);

    const int M = BB * NN;   // 4096
    dim3 tb(32, 8);

    // Weight transposes
    transpose_f32<<<dim3(DD / 32, DD / 32), tb>>>(Wq, pWT, DD, DD);
    transpose_f32<<<dim3((2 * HKV * HD) / 32, DD / 32), tb>>>(Wkv, pWT + (size_t)KOFF * DD, DD, 2 * HKV * HD);
    transpose_f32<<<dim3(DD / 32, DD / 32), tb>>>(Wo, pWoT, DD, DD);

    // QKV GEMM with register-RoPE fused epilogue (paired B mapping)
    gemm_qkv_fused<<<dim3(QKVW / 128, M / 128), 512, SMEM_SZ>>>(
        x, DD, pWT, DD, DD, cosb, sinb);

    // V transpose + split (from fp32 g_V)
    transpose_v_split<<<dim3(NN / 32, HD / 32, BB * HKV), tb>>>();

    // fused attention
    flash_attn<<<dim3(1, NN / 128, BB * HH), 256, F_SZ>>>(mask);

    // out = ctx @ Wo + bo
    gemm_nt_mma<<<dim3(DD / 128, M / 128), 512, SMEM_SZ>>>(pCtx, HH * HD, pWoT, DD, out, DD, DD, bo);
}